// round 2
// baseline (speedup 1.0000x reference)
#include <cuda_runtime.h>
#include <math.h>

// Problem constants
#define B_    2
#define Q_    1024
#define H_    32
#define KVH_  8
#define D_    128
#define KV_   4096
#define HID_  4096
#define NREP_ (H_ / KVH_)
#define M_    (B_ * Q_)              // 2048
#define QKVN_ ((H_ + 2 * KVH_) * D_) // 6144

#define HDP 132   // padded smem row stride (floats) for 128-wide tiles
#define SP  68    // padded smem row stride for 64-wide score tile

// Static device scratch (allocation-free rule)
__device__ float g_qkv[(size_t)M_ * QKVN_];            // [m][6144]
__device__ float g_q  [(size_t)B_ * H_  * Q_  * D_];   // [b][h][q][d]
__device__ float g_k  [(size_t)B_ * KVH_ * KV_ * D_];  // [b][kvh][kv][d]
__device__ float g_v  [(size_t)B_ * KVH_ * KV_ * D_];
__device__ float g_attn[(size_t)M_ * H_ * D_];         // [m][h*d]

// ---------------------------------------------------------------------------
// SGEMM: C[m][n] = sum_k A[m][k] * W[n][k]
// A: M x K row-major (ld = K). W: N x K row-major (ld = K). C: ld = ldc.
// 128x128 block tile, BK=8, 256 threads, 8x8 per-thread micro-tile.
// ---------------------------------------------------------------------------
__global__ __launch_bounds__(256) void sgemm_nt(
    const float* __restrict__ A, const float* __restrict__ W,
    float* __restrict__ C, int K, int ldc)
{
    __shared__ float As[8][HDP];
    __shared__ float Bs[8][HDP];
    const int tid = threadIdx.x;
    const int bm = blockIdx.y * 128, bn = blockIdx.x * 128;
    const int lr = tid >> 1;          // 0..127 tile row
    const int lc = (tid & 1) * 4;     // 0 or 4  k-offset
    const int tx = tid & 15, ty = tid >> 4;

    const float* Ap = A + (size_t)(bm + lr) * K + lc;
    const float* Wp = W + (size_t)(bn + lr) * K + lc;

    float acc[8][8];
#pragma unroll
    for (int i = 0; i < 8; i++)
#pragma unroll
        for (int j = 0; j < 8; j++) acc[i][j] = 0.f;

    for (int k0 = 0; k0 < K; k0 += 8) {
        float4 av = *(const float4*)(Ap + k0);
        float4 wv = *(const float4*)(Wp + k0);
        As[lc + 0][lr] = av.x; As[lc + 1][lr] = av.y;
        As[lc + 2][lr] = av.z; As[lc + 3][lr] = av.w;
        Bs[lc + 0][lr] = wv.x; Bs[lc + 1][lr] = wv.y;
        Bs[lc + 2][lr] = wv.z; Bs[lc + 3][lr] = wv.w;
        __syncthreads();
#pragma unroll
        for (int kk = 0; kk < 8; kk++) {
            float4 a0 = *(const float4*)&As[kk][ty * 8];
            float4 a1 = *(const float4*)&As[kk][ty * 8 + 4];
            float4 b0 = *(const float4*)&Bs[kk][tx * 8];
            float4 b1 = *(const float4*)&Bs[kk][tx * 8 + 4];
            float ar[8] = {a0.x, a0.y, a0.z, a0.w, a1.x, a1.y, a1.z, a1.w};
            float br[8] = {b0.x, b0.y, b0.z, b0.w, b1.x, b1.y, b1.z, b1.w};
#pragma unroll
            for (int i = 0; i < 8; i++)
#pragma unroll
                for (int j = 0; j < 8; j++) acc[i][j] += ar[i] * br[j];
        }
        __syncthreads();
    }
#pragma unroll
    for (int i = 0; i < 8; i++) {
        float* cp = C + (size_t)(bm + ty * 8 + i) * ldc + bn + tx * 8;
        *(float4*)cp       = make_float4(acc[i][0], acc[i][1], acc[i][2], acc[i][3]);
        *(float4*)(cp + 4) = make_float4(acc[i][4], acc[i][5], acc[i][6], acc[i][7]);
    }
}

// ---------------------------------------------------------------------------
// Copy KV caches into scratch (scatter overwrites sink rows afterwards)
// ---------------------------------------------------------------------------
__global__ void copy_caches(const float4* __restrict__ ck, const float4* __restrict__ cv)
{
    const int n = B_ * KVH_ * KV_ * D_ / 4;
    float4* dk = (float4*)g_k;
    float4* dv = (float4*)g_v;
    for (int i = blockIdx.x * blockDim.x + threadIdx.x; i < n;
         i += gridDim.x * blockDim.x) {
        dk[i] = ck[i];
        dv[i] = cv[i];
    }
}

// ---------------------------------------------------------------------------
// RoPE on Q/K, scale Q by 1/sqrt(D), scatter K/V into cache scratch at sink_ids
// One thread per (b, q, head(48), d) element.
// ---------------------------------------------------------------------------
__global__ void rope_scatter(const float* __restrict__ cosp,
                             const float* __restrict__ sinp,
                             const int*   __restrict__ sink)
{
    int idx = blockIdx.x * blockDim.x + threadIdx.x;
    const int total = B_ * Q_ * (H_ + 2 * KVH_) * D_;
    if (idx >= total) return;
    int d = idx & (D_ - 1);
    int t = idx >> 7;
    int head = t % (H_ + 2 * KVH_); t /= (H_ + 2 * KVH_);
    int q = t % Q_;
    int b = t / Q_;
    const float* row = g_qkv + (size_t)(b * Q_ + q) * QKVN_;

    if (head < H_ + KVH_) {
        float c = cosp[(size_t)(b * Q_ + q) * D_ + d];
        float s = sinp[(size_t)(b * Q_ + q) * D_ + d];
        int off = (head < H_) ? head * D_ : (H_ * D_ + (head - H_) * D_);
        float x  = row[off + d];
        float xp = (d < D_ / 2) ? row[off + d + D_ / 2] : row[off + d - D_ / 2];
        float r  = (d < D_ / 2) ? (x * c - xp * s) : (x * c + xp * s);
        if (head < H_) {
            // Q: scaled by 1/sqrt(128)
            g_q[((size_t)(b * H_ + head) * Q_ + q) * D_ + d] = r * 0.08838834764831845f;
        } else {
            int kvh = head - H_;
            int sid = sink[q];
            g_k[((size_t)(b * KVH_ + kvh) * KV_ + sid) * D_ + d] = r;
        }
    } else {
        int kvh = head - H_ - KVH_;
        int sid = sink[q];
        g_v[((size_t)(b * KVH_ + kvh) * KV_ + sid) * D_ + d] =
            row[(H_ + KVH_) * D_ + kvh * D_ + d];
    }
}

// ---------------------------------------------------------------------------
// Flash attention, fp32. Block = (64 q-rows, one (b,h)). 256 threads.
// KV tiles of 64. Online softmax. Output -> g_attn [b*Q][h*D] for final GEMM.
// ---------------------------------------------------------------------------
__global__ __launch_bounds__(256, 1) void attn_kernel(const float* __restrict__ mask)
{
    extern __shared__ float sm[];
    float* sQ = sm;                    // 64 * HDP
    float* sK = sQ + 64 * HDP;         // 64 * HDP
    float* sV = sK + 64 * HDP;         // 64 * HDP
    float* sS = sV + 64 * HDP;         // 64 * SP

    const int tid = threadIdx.x;
    const int b = blockIdx.z, h = blockIdx.y, q0 = blockIdx.x * 64;
    const int kvh = h / NREP_;
    const float* Qg   = g_q + ((size_t)(b * H_ + h) * Q_ + q0) * D_;
    const float* Kb   = g_k + (size_t)(b * KVH_ + kvh) * KV_ * D_;
    const float* Vb   = g_v + (size_t)(b * KVH_ + kvh) * KV_ * D_;
    const float* mrow = mask + ((size_t)b * Q_ + q0) * KV_;

    // load Q tile (with padded stride)
    for (int i = tid; i < 64 * (D_ / 4); i += 256) {
        int r = i >> 5, c = i & 31;
        ((float4*)sQ)[r * (HDP / 4) + c] = ((const float4*)Qg)[i];
    }

    const int tx = tid & 15, ty = tid >> 4;    // S-phase mapping
    const int row = tid >> 2, dch = (tid & 3) * 32;  // softmax/PV mapping
    float m_i = -1e30f, l_i = 0.f;
    float accO[32];
#pragma unroll
    for (int i = 0; i < 32; i++) accO[i] = 0.f;

    for (int t = 0; t < KV_ / 64; t++) {
        const int j0 = t * 64;
        __syncthreads();   // prev-iter readers of sK/sV/sS done
        const float4* Kg = (const float4*)(Kb + (size_t)j0 * D_);
        const float4* Vg = (const float4*)(Vb + (size_t)j0 * D_);
        for (int i = tid; i < 64 * 32; i += 256) {
            int r = i >> 5, c = i & 31;
            ((float4*)sK)[r * (HDP / 4) + c] = Kg[i];
            ((float4*)sV)[r * (HDP / 4) + c] = Vg[i];
        }
        __syncthreads();

        // S = Qtile @ Ktile^T  (Q pre-scaled). Thread: rows ty*4+r, cols tx+16*c
        float s[4][4];
#pragma unroll
        for (int r = 0; r < 4; r++)
#pragma unroll
            for (int c = 0; c < 4; c++) s[r][c] = 0.f;
#pragma unroll 4
        for (int kk = 0; kk < D_; kk += 4) {
            float4 qa[4], kb4[4];
#pragma unroll
            for (int r = 0; r < 4; r++)
                qa[r] = *(const float4*)&sQ[(ty * 4 + r) * HDP + kk];
#pragma unroll
            for (int c = 0; c < 4; c++)
                kb4[c] = *(const float4*)&sK[(tx + 16 * c) * HDP + kk];
#pragma unroll
            for (int r = 0; r < 4; r++)
#pragma unroll
                for (int c = 0; c < 4; c++)
                    s[r][c] += qa[r].x * kb4[c].x + qa[r].y * kb4[c].y
                             + qa[r].z * kb4[c].z + qa[r].w * kb4[c].w;
        }
#pragma unroll
        for (int r = 0; r < 4; r++)
#pragma unroll
            for (int c = 0; c < 4; c++) {
                int i = ty * 4 + r, j = tx + 16 * c;
                sS[i * SP + j] = s[r][c] + mrow[(size_t)i * KV_ + j0 + j];
            }
        __syncthreads();

        // online softmax: quad of 4 threads per row, 16 cols each
        float* srow = sS + row * SP + (tid & 3) * 16;
        float mx = -1e30f;
#pragma unroll
        for (int jj = 0; jj < 16; jj++) mx = fmaxf(mx, srow[jj]);
        mx = fmaxf(mx, __shfl_xor_sync(0xffffffffu, mx, 1));
        mx = fmaxf(mx, __shfl_xor_sync(0xffffffffu, mx, 2));
        float m_new = fmaxf(m_i, mx);
        float ssum = 0.f;
#pragma unroll
        for (int jj = 0; jj < 16; jj++) {
            float e = __expf(srow[jj] - m_new);
            srow[jj] = e;
            ssum += e;
        }
        ssum += __shfl_xor_sync(0xffffffffu, ssum, 1);
        ssum += __shfl_xor_sync(0xffffffffu, ssum, 2);
        float corr = __expf(m_i - m_new);
        l_i = l_i * corr + ssum;
        m_i = m_new;
#pragma unroll
        for (int i = 0; i < 32; i++) accO[i] *= corr;
        __syncwarp();   // row's exp() writes come from same-warp quad

        // O += P @ Vtile : thread owns (row, 32 d-cols)
        const float* prow = sS + row * SP;
#pragma unroll 4
        for (int j = 0; j < 64; j++) {
            float p = prow[j];
            const float* v = sV + j * HDP + dch;
#pragma unroll
            for (int dd = 0; dd < 32; dd += 4) {
                float4 vv = *(const float4*)(v + dd);
                accO[dd]     += p * vv.x;
                accO[dd + 1] += p * vv.y;
                accO[dd + 2] += p * vv.z;
                accO[dd + 3] += p * vv.w;
            }
        }
    }

    float inv = 1.f / l_i;
    float* op = g_attn + (size_t)(b * Q_ + q0 + row) * (H_ * D_) + h * D_ + dch;
#pragma unroll
    for (int dd = 0; dd < 32; dd += 4)
        *(float4*)(op + dd) = make_float4(accO[dd] * inv, accO[dd + 1] * inv,
                                          accO[dd + 2] * inv, accO[dd + 3] * inv);
}

// ---------------------------------------------------------------------------
extern "C" void kernel_launch(void* const* d_in, const int* in_sizes, int n_in,
                              void* d_out, int out_size)
{
    const float* hidden = (const float*)d_in[0];
    const float* cosp   = (const float*)d_in[1];
    const float* sinp   = (const float*)d_in[2];
    const float* mask   = (const float*)d_in[3];
    const float* ck     = (const float*)d_in[4];
    const float* cv     = (const float*)d_in[5];
    const int*   sink   = (const int*)d_in[6];
    const float* Wq     = (const float*)d_in[7];
    const float* Wk     = (const float*)d_in[8];
    const float* Wv     = (const float*)d_in[9];
    const float* Wo     = (const float*)d_in[10];
    float* out = (float*)d_out;

    float *qkv_p = nullptr, *attn_p = nullptr;
    cudaGetSymbolAddress((void**)&qkv_p, g_qkv);
    cudaGetSymbolAddress((void**)&attn_p, g_attn);

    // QKV projections into g_qkv columns [0:4096 | 4096:5120 | 5120:6144]
    sgemm_nt<<<dim3(HID_ / 128, M_ / 128), 256>>>(hidden, Wq, qkv_p, HID_, QKVN_);
    sgemm_nt<<<dim3((KVH_ * D_) / 128, M_ / 128), 256>>>(hidden, Wk, qkv_p + H_ * D_, HID_, QKVN_);
    sgemm_nt<<<dim3((KVH_ * D_) / 128, M_ / 128), 256>>>(hidden, Wv, qkv_p + (H_ + KVH_) * D_, HID_, QKVN_);

    // KV cache copy + RoPE/scatter
    copy_caches<<<2048, 256>>>((const float4*)ck, (const float4*)cv);
    {
        int total = B_ * Q_ * (H_ + 2 * KVH_) * D_;
        rope_scatter<<<(total + 255) / 256, 256>>>(cosp, sinp, sink);
    }

    // Attention
    size_t smem_attn = (size_t)(3 * 64 * HDP + 64 * SP) * sizeof(float);
    cudaFuncSetAttribute(attn_kernel, cudaFuncAttributeMaxDynamicSharedMemorySize,
                         (int)smem_attn);
    attn_kernel<<<dim3(Q_ / 64, H_, B_), 256, smem_attn>>>(mask);

    // Output projection -> d_out
    sgemm_nt<<<dim3(HID_ / 128, M_ / 128), 256>>>(attn_p, Wo, out, H_ * D_, HID_);
}

// round 5
// speedup vs baseline: 7.1635x; 7.1635x over previous
#include <cuda_runtime.h>
#include <math.h>
#include <stdint.h>

// Problem constants
#define B_    2
#define Q_    1024
#define H_    32
#define KVH_  8
#define D_    128
#define KV_   4096
#define HID_  4096
#define NREP_ (H_ / KVH_)
#define M_    (B_ * Q_)              // 2048
#define QKVN_ ((H_ + 2 * KVH_) * D_) // 6144

// Static device scratch (allocation-free rule)
__device__ float g_qkv[(size_t)M_ * QKVN_];            // [m][6144]
__device__ float g_q  [(size_t)B_ * H_  * Q_  * D_];   // [b][h][q][d], pre-scaled
__device__ float g_k  [(size_t)B_ * KVH_ * KV_ * D_];  // [b][kvh][kv][d]
__device__ float g_v  [(size_t)B_ * KVH_ * KV_ * D_];
__device__ float g_attn[(size_t)M_ * H_ * D_];         // [m][h*d]

// ---------------------------------------------------------------------------
// helpers
// ---------------------------------------------------------------------------
__device__ __forceinline__ float tf32r(float x) {
    uint32_t u;
    asm("cvt.rna.tf32.f32 %0, %1;" : "=r"(u) : "f"(x));
    return __uint_as_float(u);
}

__device__ __forceinline__ void mma8(float c[4], const uint32_t a[4], const uint32_t b[2]) {
    asm volatile(
        "mma.sync.aligned.m16n8k8.row.col.f32.tf32.tf32.f32 "
        "{%0,%1,%2,%3}, {%4,%5,%6,%7}, {%8,%9}, {%0,%1,%2,%3};\n"
        : "+f"(c[0]), "+f"(c[1]), "+f"(c[2]), "+f"(c[3])
        : "r"(a[0]), "r"(a[1]), "r"(a[2]), "r"(a[3]), "r"(b[0]), "r"(b[1]));
}

// ---------------------------------------------------------------------------
// TF32 GEMM: C[m][n] = sum_k A[m][k] * W[n][k]
// Block 128x128, BK=32, 256 threads (8 warps, 4x2 warp grid, 32x64 warp tile).
// smem pad to 36 floats/row (36 % 32 == 4 -> conflict-free fragment loads).
// ---------------------------------------------------------------------------
#define GP 36
__global__ __launch_bounds__(256) void gemm_tf32(
    const float* __restrict__ A, const float* __restrict__ W,
    float* __restrict__ C, int K, int ldc)
{
    extern __shared__ float sm[];
    float* As = sm;                 // [2][128][GP]
    float* Bs = sm + 2 * 128 * GP;  // [2][128][GP]

    const int tid = threadIdx.x;
    const int lane = tid & 31, wid = tid >> 5;
    const int warp_m = wid & 3, warp_n = wid >> 2;
    const int g = lane >> 2, t = lane & 3;
    const int bm = blockIdx.y * 128, bn = blockIdx.x * 128;

    const int r0 = tid >> 3;          // + 32*i
    const int c0 = (tid & 7) * 4;

    const float* Ap = A + (size_t)(bm + r0) * K + c0;
    const float* Wp = W + (size_t)(bn + r0) * K + c0;

    float acc[2][8][4];
#pragma unroll
    for (int mt = 0; mt < 2; mt++)
#pragma unroll
        for (int nt = 0; nt < 8; nt++)
#pragma unroll
            for (int i = 0; i < 4; i++) acc[mt][nt][i] = 0.f;

    float4 ra[4], rb[4];
#pragma unroll
    for (int i = 0; i < 4; i++) {
        ra[i] = *(const float4*)(Ap + (size_t)(32 * i) * K);
        rb[i] = *(const float4*)(Wp + (size_t)(32 * i) * K);
    }
    // store stage 0
    {
        float* as = As;
        float* bs = Bs;
#pragma unroll
        for (int i = 0; i < 4; i++) {
            float* p = as + (r0 + 32 * i) * GP + c0;
            p[0] = tf32r(ra[i].x); p[1] = tf32r(ra[i].y);
            p[2] = tf32r(ra[i].z); p[3] = tf32r(ra[i].w);
            p = bs + (r0 + 32 * i) * GP + c0;
            p[0] = tf32r(rb[i].x); p[1] = tf32r(rb[i].y);
            p[2] = tf32r(rb[i].z); p[3] = tf32r(rb[i].w);
        }
    }
    __syncthreads();

    const int nstage = K / 32;
    int buf = 0;
    for (int s = 0; s < nstage; s++) {
        if (s + 1 < nstage) {
            const float* Ap2 = Ap + (size_t)(s + 1) * 32;
            const float* Wp2 = Wp + (size_t)(s + 1) * 32;
#pragma unroll
            for (int i = 0; i < 4; i++) {
                ra[i] = *(const float4*)(Ap2 + (size_t)(32 * i) * K);
                rb[i] = *(const float4*)(Wp2 + (size_t)(32 * i) * K);
            }
        }
        const float* as = As + buf * 128 * GP;
        const float* bs = Bs + buf * 128 * GP;
#pragma unroll
        for (int ks = 0; ks < 4; ks++) {
            uint32_t af[2][4], bf[8][2];
#pragma unroll
            for (int mt = 0; mt < 2; mt++) {
                const float* ap = as + (warp_m * 32 + mt * 16) * GP + ks * 8;
                af[mt][0] = __float_as_uint(ap[g * GP + t]);
                af[mt][1] = __float_as_uint(ap[(g + 8) * GP + t]);
                af[mt][2] = __float_as_uint(ap[g * GP + t + 4]);
                af[mt][3] = __float_as_uint(ap[(g + 8) * GP + t + 4]);
            }
#pragma unroll
            for (int nt = 0; nt < 8; nt++) {
                const float* bp = bs + (warp_n * 64 + nt * 8 + g) * GP + ks * 8;
                bf[nt][0] = __float_as_uint(bp[t]);
                bf[nt][1] = __float_as_uint(bp[t + 4]);
            }
#pragma unroll
            for (int mt = 0; mt < 2; mt++)
#pragma unroll
                for (int nt = 0; nt < 8; nt++) mma8(acc[mt][nt], af[mt], bf[nt]);
        }
        __syncthreads();
        if (s + 1 < nstage) {
            float* asn = As + (buf ^ 1) * 128 * GP;
            float* bsn = Bs + (buf ^ 1) * 128 * GP;
#pragma unroll
            for (int i = 0; i < 4; i++) {
                float* p = asn + (r0 + 32 * i) * GP + c0;
                p[0] = tf32r(ra[i].x); p[1] = tf32r(ra[i].y);
                p[2] = tf32r(ra[i].z); p[3] = tf32r(ra[i].w);
                p = bsn + (r0 + 32 * i) * GP + c0;
                p[0] = tf32r(rb[i].x); p[1] = tf32r(rb[i].y);
                p[2] = tf32r(rb[i].z); p[3] = tf32r(rb[i].w);
            }
            __syncthreads();
            buf ^= 1;
        }
    }

    // epilogue
#pragma unroll
    for (int mt = 0; mt < 2; mt++)
#pragma unroll
        for (int nt = 0; nt < 8; nt++) {
            int row = bm + warp_m * 32 + mt * 16 + g;
            int col = bn + warp_n * 64 + nt * 8 + 2 * t;
            *(float2*)(C + (size_t)row * ldc + col) =
                make_float2(acc[mt][nt][0], acc[mt][nt][1]);
            *(float2*)(C + (size_t)(row + 8) * ldc + col) =
                make_float2(acc[mt][nt][2], acc[mt][nt][3]);
        }
}

// ---------------------------------------------------------------------------
// Copy KV caches into scratch
// ---------------------------------------------------------------------------
__global__ void copy_caches(const float4* __restrict__ ck, const float4* __restrict__ cv)
{
    const int n = B_ * KVH_ * KV_ * D_ / 4;
    float4* dk = (float4*)g_k;
    float4* dv = (float4*)g_v;
    for (int i = blockIdx.x * blockDim.x + threadIdx.x; i < n;
         i += gridDim.x * blockDim.x) {
        dk[i] = ck[i];
        dv[i] = cv[i];
    }
}

// ---------------------------------------------------------------------------
// RoPE + scatter (Q pre-scaled by 1/sqrt(D))
// ---------------------------------------------------------------------------
__global__ void rope_scatter(const float* __restrict__ cosp,
                             const float* __restrict__ sinp,
                             const int*   __restrict__ sink)
{
    int idx = blockIdx.x * blockDim.x + threadIdx.x;
    const int total = B_ * Q_ * (H_ + 2 * KVH_) * D_;
    if (idx >= total) return;
    int d = idx & (D_ - 1);
    int t = idx >> 7;
    int head = t % (H_ + 2 * KVH_); t /= (H_ + 2 * KVH_);
    int q = t % Q_;
    int b = t / Q_;
    const float* row = g_qkv + (size_t)(b * Q_ + q) * QKVN_;

    if (head < H_ + KVH_) {
        float c = cosp[(size_t)(b * Q_ + q) * D_ + d];
        float s = sinp[(size_t)(b * Q_ + q) * D_ + d];
        int off = (head < H_) ? head * D_ : (H_ * D_ + (head - H_) * D_);
        float x  = row[off + d];
        float xp = (d < D_ / 2) ? row[off + d + D_ / 2] : row[off + d - D_ / 2];
        float r  = (d < D_ / 2) ? (x * c - xp * s) : (x * c + xp * s);
        if (head < H_) {
            g_q[((size_t)(b * H_ + head) * Q_ + q) * D_ + d] = r * 0.08838834764831845f;
        } else {
            int kvh = head - H_;
            int sid = sink[q];
            g_k[((size_t)(b * KVH_ + kvh) * KV_ + sid) * D_ + d] = r;
        }
    } else {
        int kvh = head - H_ - KVH_;
        int sid = sink[q];
        g_v[((size_t)(b * KVH_ + kvh) * KV_ + sid) * D_ + d] =
            row[(H_ + KVH_) * D_ + kvh * D_ + d];
    }
}

// ---------------------------------------------------------------------------
// Flash attention with TF32 mma. Block = 128 q-rows x one (b,h). 256 threads,
// 8 warps; warp w owns q-rows [16w, 16w+16). KV tile = 64.
// Q fragments preloaded to registers. smem: K[64][132], V[64][136], S[128][68].
// ---------------------------------------------------------------------------
#define KP 132   // 132 % 32 == 4
#define VP 136   // 136 % 32 == 8
#define SPD 68   //  68 % 32 == 4
__global__ __launch_bounds__(256, 1) void attn_mma(const float* __restrict__ mask)
{
    extern __shared__ float sm[];
    float* sK    = sm;                      // [64][KP]
    float* sV    = sK + 64 * KP;            // [64][VP]
    float* sS    = sV + 64 * VP;            // [128][SPD]
    float* scorr = sS + 128 * SPD;          // [128]
    float* slsum = scorr + 128;             // [128]

    const int tid = threadIdx.x, lane = tid & 31, w = tid >> 5;
    const int b = blockIdx.z, h = blockIdx.y, q0 = blockIdx.x * 128;
    const int kvh = h / NREP_;
    const int g = lane >> 2, t = lane & 3;

    // preload Q fragments (rounded to tf32)
    const float* Qg = g_q + ((size_t)(b * H_ + h) * Q_ + q0 + w * 16) * D_;
    uint32_t qf[16][4];
#pragma unroll
    for (int ks = 0; ks < 16; ks++) {
        qf[ks][0] = __float_as_uint(tf32r(Qg[(size_t)g * D_ + ks * 8 + t]));
        qf[ks][1] = __float_as_uint(tf32r(Qg[(size_t)(g + 8) * D_ + ks * 8 + t]));
        qf[ks][2] = __float_as_uint(tf32r(Qg[(size_t)g * D_ + ks * 8 + t + 4]));
        qf[ks][3] = __float_as_uint(tf32r(Qg[(size_t)(g + 8) * D_ + ks * 8 + t + 4]));
    }

    float accO[16][4];
#pragma unroll
    for (int nt = 0; nt < 16; nt++)
#pragma unroll
        for (int i = 0; i < 4; i++) accO[nt][i] = 0.f;

    // softmax-phase mapping: row = tid/2, half = tid&1 (32 cols each)
    const int srow = tid >> 1, shalf = tid & 1;
    float m_i = -1e30f, l_i = 0.f;

    const float* Kb = g_k + (size_t)(b * KVH_ + kvh) * KV_ * D_;
    const float* Vb = g_v + (size_t)(b * KVH_ + kvh) * KV_ * D_;
    const float* mbase = mask + ((size_t)b * Q_ + q0) * KV_;

    for (int it = 0; it < KV_ / 64; it++) {
        const int j0 = it * 64;
        __syncthreads();   // previous O-phase done with sV/sS
        {
            const float4* Kg = (const float4*)(Kb + (size_t)j0 * D_);
            const float4* Vg = (const float4*)(Vb + (size_t)j0 * D_);
#pragma unroll
            for (int i = 0; i < 8; i++) {
                int v = tid + 256 * i;
                int r = v >> 5, c4 = (v & 31) * 4;
                float4 kv4 = Kg[v];
                float* p = sK + r * KP + c4;
                p[0] = tf32r(kv4.x); p[1] = tf32r(kv4.y);
                p[2] = tf32r(kv4.z); p[3] = tf32r(kv4.w);
                float4 vv4 = Vg[v];
                p = sV + r * VP + c4;
                p[0] = tf32r(vv4.x); p[1] = tf32r(vv4.y);
                p[2] = tf32r(vv4.z); p[3] = tf32r(vv4.w);
            }
        }
        __syncthreads();

        // ---- S = Q @ K^T (warp: 16 rows x 64 cols) ----
        float sacc[8][4];
#pragma unroll
        for (int nt = 0; nt < 8; nt++)
#pragma unroll
            for (int i = 0; i < 4; i++) sacc[nt][i] = 0.f;
#pragma unroll
        for (int ks = 0; ks < 16; ks++) {
            uint32_t bf[8][2];
#pragma unroll
            for (int nt = 0; nt < 8; nt++) {
                const float* kp = sK + (nt * 8 + g) * KP + ks * 8 + t;
                bf[nt][0] = __float_as_uint(kp[0]);
                bf[nt][1] = __float_as_uint(kp[4]);
            }
#pragma unroll
            for (int nt = 0; nt < 8; nt++) mma8(sacc[nt], qf[ks], bf[nt]);
        }
        // write S + mask to smem
        {
            int r0 = w * 16 + g;
#pragma unroll
            for (int nt = 0; nt < 8; nt++) {
                int col = nt * 8 + 2 * t;
                float2 mv0 = *(const float2*)(mbase + (size_t)r0 * KV_ + j0 + col);
                float2 mv1 = *(const float2*)(mbase + (size_t)(r0 + 8) * KV_ + j0 + col);
                *(float2*)(sS + r0 * SPD + col) =
                    make_float2(sacc[nt][0] + mv0.x, sacc[nt][1] + mv0.y);
                *(float2*)(sS + (r0 + 8) * SPD + col) =
                    make_float2(sacc[nt][2] + mv1.x, sacc[nt][3] + mv1.y);
            }
        }
        __syncthreads();

        // ---- online softmax (2 threads per row) ----
        {
            float* sr = sS + srow * SPD + shalf * 32;
            float mx = -1e30f;
#pragma unroll
            for (int j = 0; j < 32; j++) mx = fmaxf(mx, sr[j]);
            mx = fmaxf(mx, __shfl_xor_sync(0xffffffffu, mx, 1));
            float m_new = fmaxf(m_i, mx);
            float ss = 0.f;
#pragma unroll
            for (int j = 0; j < 32; j++) {
                float e = __expf(sr[j] - m_new);
                ss += e;
                sr[j] = tf32r(e);
            }
            ss += __shfl_xor_sync(0xffffffffu, ss, 1);
            float corr = __expf(m_i - m_new);
            l_i = l_i * corr + ss;
            m_i = m_new;
            if (!shalf) { scorr[srow] = corr; slsum[srow] = l_i; }
        }
        __syncthreads();

        // ---- O = corr*O + P @ V ----
        {
            float c0 = scorr[w * 16 + g], c1 = scorr[w * 16 + 8 + g];
#pragma unroll
            for (int nt = 0; nt < 16; nt++) {
                accO[nt][0] *= c0; accO[nt][1] *= c0;
                accO[nt][2] *= c1; accO[nt][3] *= c1;
            }
#pragma unroll
            for (int ks = 0; ks < 8; ks++) {
                uint32_t af[4];
                const float* pp  = sS + (w * 16 + g) * SPD + ks * 8 + t;
                const float* pp8 = sS + (w * 16 + 8 + g) * SPD + ks * 8 + t;
                af[0] = __float_as_uint(pp[0]);
                af[1] = __float_as_uint(pp8[0]);
                af[2] = __float_as_uint(pp[4]);
                af[3] = __float_as_uint(pp8[4]);
#pragma unroll
                for (int nt = 0; nt < 16; nt++) {
                    uint32_t bf[2];
                    const float* vp = sV + (ks * 8 + t) * VP + nt * 8 + g;
                    bf[0] = __float_as_uint(vp[0]);
                    bf[1] = __float_as_uint(vp[4 * VP]);
                    mma8(accO[nt], af, bf);
                }
            }
        }
    }
    __syncthreads();

    float inv0 = 1.f / slsum[w * 16 + g];
    float inv1 = 1.f / slsum[w * 16 + 8 + g];
    float* op  = g_attn + (size_t)(b * Q_ + q0 + w * 16 + g) * (H_ * D_) + h * D_;
    float* op8 = g_attn + (size_t)(b * Q_ + q0 + w * 16 + 8 + g) * (H_ * D_) + h * D_;
#pragma unroll
    for (int nt = 0; nt < 16; nt++) {
        *(float2*)(op  + nt * 8 + 2 * t) =
            make_float2(accO[nt][0] * inv0, accO[nt][1] * inv0);
        *(float2*)(op8 + nt * 8 + 2 * t) =
            make_float2(accO[nt][2] * inv1, accO[nt][3] * inv1);
    }
}

// ---------------------------------------------------------------------------
extern "C" void kernel_launch(void* const* d_in, const int* in_sizes, int n_in,
                              void* d_out, int out_size)
{
    const float* hidden = (const float*)d_in[0];
    const float* cosp   = (const float*)d_in[1];
    const float* sinp   = (const float*)d_in[2];
    const float* mask   = (const float*)d_in[3];
    const float* ck     = (const float*)d_in[4];
    const float* cv     = (const float*)d_in[5];
    const int*   sink   = (const int*)d_in[6];
    const float* Wq     = (const float*)d_in[7];
    const float* Wk     = (const float*)d_in[8];
    const float* Wv     = (const float*)d_in[9];
    const float* Wo     = (const float*)d_in[10];
    float* out = (float*)d_out;

    float *qkv_p = nullptr, *attn_p = nullptr;
    cudaGetSymbolAddress((void**)&qkv_p, g_qkv);
    cudaGetSymbolAddress((void**)&attn_p, g_attn);

    size_t smem_gemm = (size_t)(4 * 128 * GP) * sizeof(float);  // 73728
    cudaFuncSetAttribute(gemm_tf32, cudaFuncAttributeMaxDynamicSharedMemorySize,
                         (int)smem_gemm);

    // QKV projections into g_qkv columns [0:4096 | 4096:5120 | 5120:6144]
    gemm_tf32<<<dim3(HID_ / 128, M_ / 128), 256, smem_gemm>>>(hidden, Wq, qkv_p, HID_, QKVN_);
    gemm_tf32<<<dim3((KVH_ * D_) / 128, M_ / 128), 256, smem_gemm>>>(hidden, Wk, qkv_p + H_ * D_, HID_, QKVN_);
    gemm_tf32<<<dim3((KVH_ * D_) / 128, M_ / 128), 256, smem_gemm>>>(hidden, Wv, qkv_p + (H_ + KVH_) * D_, HID_, QKVN_);

    // KV cache copy + RoPE/scatter
    copy_caches<<<2048, 256>>>((const float4*)ck, (const float4*)cv);
    {
        int total = B_ * Q_ * (H_ + 2 * KVH_) * D_;
        rope_scatter<<<(total + 255) / 256, 256>>>(cosp, sinp, sink);
    }

    // Attention
    size_t smem_attn = (size_t)(64 * KP + 64 * VP + 128 * SPD + 256) * sizeof(float);
    cudaFuncSetAttribute(attn_mma, cudaFuncAttributeMaxDynamicSharedMemorySize,
                         (int)smem_attn);
    attn_mma<<<dim3(Q_ / 128, H_, B_), 256, smem_attn>>>(mask);

    // Output projection -> d_out
    gemm_tf32<<<dim3(HID_ / 128, M_ / 128), 256, smem_gemm>>>(attn_p, Wo, out, H_ * D_, HID_);
}

// round 11
// speedup vs baseline: 8.1830x; 1.1423x over previous
#include <cuda_runtime.h>
#include <math.h>
#include <stdint.h>

// Problem constants
#define B_    2
#define Q_    1024
#define H_    32
#define KVH_  8
#define D_    128
#define KV_   4096
#define HID_  4096
#define NREP_ (H_ / KVH_)
#define M_    (B_ * Q_)              // 2048
#define QKVN_ ((H_ + 2 * KVH_) * D_) // 6144

// Static device scratch (allocation-free rule)
__device__ float g_qkv[(size_t)M_ * QKVN_];            // [m][6144]
__device__ float g_q  [(size_t)B_ * H_  * Q_  * D_];   // [b][h][q][d], pre-scaled
__device__ float g_k  [(size_t)B_ * KVH_ * KV_ * D_];  // [b][kvh][kv][d]
__device__ float g_v  [(size_t)B_ * KVH_ * KV_ * D_];
__device__ float g_attn[(size_t)M_ * H_ * D_];         // [m][h*d]

// ---------------------------------------------------------------------------
// helpers
// ---------------------------------------------------------------------------
__device__ __forceinline__ float tf32r(float x) {
    uint32_t u;
    asm("cvt.rna.tf32.f32 %0, %1;" : "=r"(u) : "f"(x));
    return __uint_as_float(u);
}

__device__ __forceinline__ void mma8(float c[4], const uint32_t a[4], const uint32_t b[2]) {
    asm volatile(
        "mma.sync.aligned.m16n8k8.row.col.f32.tf32.tf32.f32 "
        "{%0,%1,%2,%3}, {%4,%5,%6,%7}, {%8,%9}, {%0,%1,%2,%3};\n"
        : "+f"(c[0]), "+f"(c[1]), "+f"(c[2]), "+f"(c[3])
        : "r"(a[0]), "r"(a[1]), "r"(a[2]), "r"(a[3]), "r"(b[0]), "r"(b[1]));
}

__device__ __forceinline__ uint32_t smem_u32(const void* p) {
    return (uint32_t)__cvta_generic_to_shared(p);
}

// ldmatrix x4 (b16 shape, but delivers 32-bit words: lane L <- row L/4, word L%4
// of each 8x16B subtile -- exactly the tf32 mma fragment layout)
__device__ __forceinline__ void ldsm4(uint32_t& r0, uint32_t& r1, uint32_t& r2,
                                      uint32_t& r3, uint32_t addr) {
    asm volatile("ldmatrix.sync.aligned.m8n8.x4.shared.b16 {%0,%1,%2,%3}, [%4];"
                 : "=r"(r0), "=r"(r1), "=r"(r2), "=r"(r3) : "r"(addr));
}

// ---------------------------------------------------------------------------
// TF32 GEMM via mma.sync + ldmatrix.
// C[m][n] = sum_k A[m][k] * W[n][k].  Block tile 256x128, BK=32, 256 threads.
// 8 warps as 4x2 grid of 64x64 warp tiles (4 mt x 8 nt).  W selected from
// {W0,W1,W2} by block column (fused QKV).  smem pitch 36 floats (conflict-free
// for both STS and LDSM).  One __syncthreads per K-stage; global prefetch in
// registers overlaps the MMA chain.
// ---------------------------------------------------------------------------
#define GP2 36
__global__ __launch_bounds__(256) void gemm_ldsm(
    const float* __restrict__ A,
    const float* __restrict__ W0, const float* __restrict__ W1,
    const float* __restrict__ W2, int nb1, int nb2,
    float* __restrict__ C, int K, int ldc)
{
    extern __shared__ float sm[];
    float* As = sm;                   // [2][256][GP2]
    float* Bs = sm + 2 * 256 * GP2;   // [2][128][GP2]

    const int tid = threadIdx.x, lane = tid & 31, wid = tid >> 5;
    const int wm = wid >> 1, wn = wid & 1;
    const int bni = blockIdx.x;
    const int bm = blockIdx.y * 256;

    const float* W;
    int bnl;
    if (bni < nb1)      { W = W0; bnl = bni * 128; }
    else if (bni < nb2) { W = W1; bnl = (bni - nb1) * 128; }
    else                { W = W2; bnl = (bni - nb2) * 128; }

    const int r8 = tid >> 3, cj = tid & 7;
    const float* Ap = A + (size_t)(bm + r8) * K + cj * 4;
    const float* Wp = W + (size_t)(bnl + r8) * K + cj * 4;

    float acc[4][8][4];
#pragma unroll
    for (int mt = 0; mt < 4; mt++)
#pragma unroll
        for (int nt = 0; nt < 8; nt++)
#pragma unroll
            for (int i = 0; i < 4; i++) acc[mt][nt][i] = 0.f;

    const uint32_t asb = smem_u32(As), bsb = smem_u32(Bs);
    const int lrow = lane & 15, lcw = (lane >> 4) << 2;

    // prologue: stage 0
    {
#pragma unroll
        for (int i = 0; i < 8; i++) {
            float4 a = *(const float4*)(Ap + (size_t)(i * 32) * K);
            float* p = As + (r8 + i * 32) * GP2 + cj * 4;
            p[0] = tf32r(a.x); p[1] = tf32r(a.y); p[2] = tf32r(a.z); p[3] = tf32r(a.w);
        }
#pragma unroll
        for (int i = 0; i < 4; i++) {
            float4 w = *(const float4*)(Wp + (size_t)(i * 32) * K);
            float* p = Bs + (r8 + i * 32) * GP2 + cj * 4;
            p[0] = tf32r(w.x); p[1] = tf32r(w.y); p[2] = tf32r(w.z); p[3] = tf32r(w.w);
        }
    }
    __syncthreads();

    const int nst = K / 32;
    for (int s = 0; s < nst; s++) {
        const int b = s & 1;
        float4 ra[8], rb[4];
        if (s + 1 < nst) {
            const int k0 = (s + 1) * 32;
#pragma unroll
            for (int i = 0; i < 8; i++)
                ra[i] = *(const float4*)(Ap + (size_t)(i * 32) * K + k0);
#pragma unroll
            for (int i = 0; i < 4; i++)
                rb[i] = *(const float4*)(Wp + (size_t)(i * 32) * K + k0);
        }

        const uint32_t abase = asb + (uint32_t)(b * 256 * GP2 + wm * 64 * GP2) * 4;
        const uint32_t bbase = bsb + (uint32_t)(b * 128 * GP2 + wn * 64 * GP2) * 4;
#pragma unroll
        for (int ks = 0; ks < 4; ks++) {
            uint32_t af[4][4], bf[8][2];
#pragma unroll
            for (int mt = 0; mt < 4; mt++)
                ldsm4(af[mt][0], af[mt][1], af[mt][2], af[mt][3],
                      abase + (uint32_t)((mt * 16 + lrow) * GP2 + ks * 8 + lcw) * 4);
#pragma unroll
            for (int p = 0; p < 4; p++) {
                uint32_t r0, r1, r2, r3;
                ldsm4(r0, r1, r2, r3,
                      bbase + (uint32_t)((p * 16 + lrow) * GP2 + ks * 8 + lcw) * 4);
                bf[2 * p][0] = r0; bf[2 * p + 1][0] = r1;
                bf[2 * p][1] = r2; bf[2 * p + 1][1] = r3;
            }
#pragma unroll
            for (int mt = 0; mt < 4; mt++)
#pragma unroll
                for (int nt = 0; nt < 8; nt++) mma8(acc[mt][nt], af[mt], bf[nt]);
        }

        if (s + 1 < nst) {
            float* as = As + (b ^ 1) * 256 * GP2;
            float* bs = Bs + (b ^ 1) * 128 * GP2;
#pragma unroll
            for (int i = 0; i < 8; i++) {
                float* p = as + (r8 + i * 32) * GP2 + cj * 4;
                p[0] = tf32r(ra[i].x); p[1] = tf32r(ra[i].y);
                p[2] = tf32r(ra[i].z); p[3] = tf32r(ra[i].w);
            }
#pragma unroll
            for (int i = 0; i < 4; i++) {
                float* p = bs + (r8 + i * 32) * GP2 + cj * 4;
                p[0] = tf32r(rb[i].x); p[1] = tf32r(rb[i].y);
                p[2] = tf32r(rb[i].z); p[3] = tf32r(rb[i].w);
            }
        }
        __syncthreads();
    }

    // epilogue
    const int g = lane >> 2, t = lane & 3;
#pragma unroll
    for (int mt = 0; mt < 4; mt++)
#pragma unroll
        for (int nt = 0; nt < 8; nt++) {
            int row = bm + wm * 64 + mt * 16 + g;
            int col = bni * 128 + wn * 64 + nt * 8 + 2 * t;
            *(float2*)(C + (size_t)row * ldc + col) =
                make_float2(acc[mt][nt][0], acc[mt][nt][1]);
            *(float2*)(C + (size_t)(row + 8) * ldc + col) =
                make_float2(acc[mt][nt][2], acc[mt][nt][3]);
        }
}

// ---------------------------------------------------------------------------
// Copy KV caches into scratch
// ---------------------------------------------------------------------------
__global__ void copy_caches(const float4* __restrict__ ck, const float4* __restrict__ cv)
{
    const int n = B_ * KVH_ * KV_ * D_ / 4;
    float4* dk = (float4*)g_k;
    float4* dv = (float4*)g_v;
    for (int i = blockIdx.x * blockDim.x + threadIdx.x; i < n;
         i += gridDim.x * blockDim.x) {
        dk[i] = ck[i];
        dv[i] = cv[i];
    }
}

// ---------------------------------------------------------------------------
// RoPE + scatter (Q pre-scaled by 1/sqrt(D))
// ---------------------------------------------------------------------------
__global__ void rope_scatter(const float* __restrict__ cosp,
                             const float* __restrict__ sinp,
                             const int*   __restrict__ sink)
{
    int idx = blockIdx.x * blockDim.x + threadIdx.x;
    const int total = B_ * Q_ * (H_ + 2 * KVH_) * D_;
    if (idx >= total) return;
    int d = idx & (D_ - 1);
    int t = idx >> 7;
    int head = t % (H_ + 2 * KVH_); t /= (H_ + 2 * KVH_);
    int q = t % Q_;
    int b = t / Q_;
    const float* row = g_qkv + (size_t)(b * Q_ + q) * QKVN_;

    if (head < H_ + KVH_) {
        float c = cosp[(size_t)(b * Q_ + q) * D_ + d];
        float s = sinp[(size_t)(b * Q_ + q) * D_ + d];
        int off = (head < H_) ? head * D_ : (H_ * D_ + (head - H_) * D_);
        float x  = row[off + d];
        float xp = (d < D_ / 2) ? row[off + d + D_ / 2] : row[off + d - D_ / 2];
        float r  = (d < D_ / 2) ? (x * c - xp * s) : (x * c + xp * s);
        if (head < H_) {
            g_q[((size_t)(b * H_ + head) * Q_ + q) * D_ + d] = r * 0.08838834764831845f;
        } else {
            int kvh = head - H_;
            int sid = sink[q];
            g_k[((size_t)(b * KVH_ + kvh) * KV_ + sid) * D_ + d] = r;
        }
    } else {
        int kvh = head - H_ - KVH_;
        int sid = sink[q];
        g_v[((size_t)(b * KVH_ + kvh) * KV_ + sid) * D_ + d] =
            row[(H_ + KVH_) * D_ + kvh * D_ + d];
    }
}

// ---------------------------------------------------------------------------
// Flash attention with TF32 mma + ldmatrix.
// Block = 128 q-rows x one (b,h). 256 threads / 8 warps.
// S-phase: warp w owns q-rows [16w,16w+16); K-frags via ldmatrix.
// P-phase: 4x2 warp grid -- warp owns 32 q-rows x 64 d-cols (halves V traffic).
// ---------------------------------------------------------------------------
#define KP 132
#define VP 136
#define SPD 68
__global__ __launch_bounds__(256, 1) void attn_mma(const float* __restrict__ mask)
{
    extern __shared__ float sm[];
    float* sK    = sm;
    float* sV    = sK + 64 * KP;
    float* sS    = sV + 64 * VP;
    float* scorr = sS + 128 * SPD;
    float* slsum = scorr + 128;

    const int tid = threadIdx.x, lane = tid & 31, w = tid >> 5;
    const int b = blockIdx.z, h = blockIdx.y, q0 = blockIdx.x * 128;
    const int kvh = h / NREP_;
    const int g = lane >> 2, t = lane & 3;
    const int lrow = lane & 15, lcw = (lane >> 4) << 2;
    const int pm = w >> 1, pn = w & 1;     // P-phase 4x2 mapping

    const uint32_t skb = smem_u32(sK), ssb = smem_u32(sS);

    // preload Q fragments (rounded to tf32)
    const float* Qg = g_q + ((size_t)(b * H_ + h) * Q_ + q0 + w * 16) * D_;
    uint32_t qf[16][4];
#pragma unroll
    for (int ks = 0; ks < 16; ks++) {
        qf[ks][0] = __float_as_uint(tf32r(Qg[(size_t)g * D_ + ks * 8 + t]));
        qf[ks][1] = __float_as_uint(tf32r(Qg[(size_t)(g + 8) * D_ + ks * 8 + t]));
        qf[ks][2] = __float_as_uint(tf32r(Qg[(size_t)g * D_ + ks * 8 + t + 4]));
        qf[ks][3] = __float_as_uint(tf32r(Qg[(size_t)(g + 8) * D_ + ks * 8 + t + 4]));
    }

    float accO[2][8][4];
#pragma unroll
    for (int mq = 0; mq < 2; mq++)
#pragma unroll
        for (int nt = 0; nt < 8; nt++)
#pragma unroll
            for (int i = 0; i < 4; i++) accO[mq][nt][i] = 0.f;

    const int srow = tid >> 1, shalf = tid & 1;
    float m_i = -1e30f, l_i = 0.f;

    const float* Kb = g_k + (size_t)(b * KVH_ + kvh) * KV_ * D_;
    const float* Vb = g_v + (size_t)(b * KVH_ + kvh) * KV_ * D_;
    const float* mbase = mask + ((size_t)b * Q_ + q0) * KV_;

    for (int it = 0; it < KV_ / 64; it++) {
        const int j0 = it * 64;
        __syncthreads();
        {
            const float4* Kg = (const float4*)(Kb + (size_t)j0 * D_);
            const float4* Vg = (const float4*)(Vb + (size_t)j0 * D_);
#pragma unroll
            for (int i = 0; i < 8; i++) {
                int v = tid + 256 * i;
                int r = v >> 5, c4 = (v & 31) * 4;
                float4 kv4 = Kg[v];
                float* p = sK + r * KP + c4;
                p[0] = tf32r(kv4.x); p[1] = tf32r(kv4.y);
                p[2] = tf32r(kv4.z); p[3] = tf32r(kv4.w);
                float4 vv4 = Vg[v];
                p = sV + r * VP + c4;
                p[0] = tf32r(vv4.x); p[1] = tf32r(vv4.y);
                p[2] = tf32r(vv4.z); p[3] = tf32r(vv4.w);
            }
        }
        __syncthreads();

        // ---- S = Q @ K^T (warp w: 16 rows x 64 cols), K-frags via ldmatrix ----
        float sacc[8][4];
#pragma unroll
        for (int nt = 0; nt < 8; nt++)
#pragma unroll
            for (int i = 0; i < 4; i++) sacc[nt][i] = 0.f;
#pragma unroll
        for (int ks = 0; ks < 16; ks++) {
            uint32_t bf[8][2];
#pragma unroll
            for (int p = 0; p < 4; p++) {
                uint32_t r0, r1, r2, r3;
                ldsm4(r0, r1, r2, r3,
                      skb + (uint32_t)((p * 16 + lrow) * KP + ks * 8 + lcw) * 4);
                bf[2 * p][0] = r0; bf[2 * p + 1][0] = r1;
                bf[2 * p][1] = r2; bf[2 * p + 1][1] = r3;
            }
#pragma unroll
            for (int nt = 0; nt < 8; nt++) mma8(sacc[nt], qf[ks], bf[nt]);
        }
        {
            int r0 = w * 16 + g;
#pragma unroll
            for (int nt = 0; nt < 8; nt++) {
                int col = nt * 8 + 2 * t;
                float2 mv0 = *(const float2*)(mbase + (size_t)r0 * KV_ + j0 + col);
                float2 mv1 = *(const float2*)(mbase + (size_t)(r0 + 8) * KV_ + j0 + col);
                *(float2*)(sS + r0 * SPD + col) =
                    make_float2(sacc[nt][0] + mv0.x, sacc[nt][1] + mv0.y);
                *(float2*)(sS + (r0 + 8) * SPD + col) =
                    make_float2(sacc[nt][2] + mv1.x, sacc[nt][3] + mv1.y);
            }
        }
        __syncthreads();

        // ---- online softmax (2 threads per row) ----
        {
            float* sr = sS + srow * SPD + shalf * 32;
            float mx = -1e30f;
#pragma unroll
            for (int j = 0; j < 32; j++) mx = fmaxf(mx, sr[j]);
            mx = fmaxf(mx, __shfl_xor_sync(0xffffffffu, mx, 1));
            float m_new = fmaxf(m_i, mx);
            float ss = 0.f;
#pragma unroll
            for (int j = 0; j < 32; j++) {
                float e = __expf(sr[j] - m_new);
                ss += e;
                sr[j] = tf32r(e);
            }
            ss += __shfl_xor_sync(0xffffffffu, ss, 1);
            float corr = __expf(m_i - m_new);
            l_i = l_i * corr + ss;
            m_i = m_new;
            if (!shalf) { scorr[srow] = corr; slsum[srow] = l_i; }
        }
        __syncthreads();

        // ---- O = corr*O + P @ V  (warp: 32 q-rows x 64 d-cols) ----
        {
            float cA = scorr[pm * 32 + g],      cB = scorr[pm * 32 + 8 + g];
            float cC = scorr[pm * 32 + 16 + g], cD = scorr[pm * 32 + 24 + g];
#pragma unroll
            for (int nt = 0; nt < 8; nt++) {
                accO[0][nt][0] *= cA; accO[0][nt][1] *= cA;
                accO[0][nt][2] *= cB; accO[0][nt][3] *= cB;
                accO[1][nt][0] *= cC; accO[1][nt][1] *= cC;
                accO[1][nt][2] *= cD; accO[1][nt][3] *= cD;
            }
#pragma unroll
            for (int ks = 0; ks < 8; ks++) {
                uint32_t af[2][4];
#pragma unroll
                for (int mq = 0; mq < 2; mq++)
                    ldsm4(af[mq][0], af[mq][1], af[mq][2], af[mq][3],
                          ssb + (uint32_t)((pm * 32 + mq * 16 + lrow) * SPD
                                           + ks * 8 + lcw) * 4);
#pragma unroll
                for (int nt = 0; nt < 8; nt++) {
                    uint32_t bf[2];
                    const float* vp = sV + (ks * 8 + t) * VP + pn * 64 + nt * 8 + g;
                    bf[0] = __float_as_uint(vp[0]);
                    bf[1] = __float_as_uint(vp[4 * VP]);
                    mma8(accO[0][nt], af[0], bf);
                    mma8(accO[1][nt], af[1], bf);
                }
            }
        }
    }
    __syncthreads();

    // ---- write O ----
#pragma unroll
    for (int mq = 0; mq < 2; mq++) {
        float i0 = 1.f / slsum[pm * 32 + mq * 16 + g];
        float i1 = 1.f / slsum[pm * 32 + mq * 16 + 8 + g];
        float* op  = g_attn + (size_t)(b * Q_ + q0 + pm * 32 + mq * 16 + g) * (H_ * D_)
                   + h * D_ + pn * 64;
        float* op8 = op + (size_t)8 * (H_ * D_);
#pragma unroll
        for (int nt = 0; nt < 8; nt++) {
            *(float2*)(op  + nt * 8 + 2 * t) =
                make_float2(accO[mq][nt][0] * i0, accO[mq][nt][1] * i0);
            *(float2*)(op8 + nt * 8 + 2 * t) =
                make_float2(accO[mq][nt][2] * i1, accO[mq][nt][3] * i1);
        }
    }
}

// ---------------------------------------------------------------------------
extern "C" void kernel_launch(void* const* d_in, const int* in_sizes, int n_in,
                              void* d_out, int out_size)
{
    const float* hidden = (const float*)d_in[0];
    const float* cosp   = (const float*)d_in[1];
    const float* sinp   = (const float*)d_in[2];
    const float* mask   = (const float*)d_in[3];
    const float* ck     = (const float*)d_in[4];
    const float* cv     = (const float*)d_in[5];
    const int*   sink   = (const int*)d_in[6];
    const float* Wq     = (const float*)d_in[7];
    const float* Wk     = (const float*)d_in[8];
    const float* Wv     = (const float*)d_in[9];
    const float* Wo     = (const float*)d_in[10];
    float* out = (float*)d_out;

    float *qkv_p = nullptr, *attn_p = nullptr;
    cudaGetSymbolAddress((void**)&qkv_p, g_qkv);
    cudaGetSymbolAddress((void**)&attn_p, g_attn);

    const int smem_gemm = (2 * 256 * GP2 + 2 * 128 * GP2) * 4;   // 110592 B
    cudaFuncSetAttribute(gemm_ldsm, cudaFuncAttributeMaxDynamicSharedMemorySize,
                         smem_gemm);

    // Fused QKV projection: one launch, N-space = [Wq 4096 | Wk 1024 | Wv 1024]
    gemm_ldsm<<<dim3(QKVN_ / 128, M_ / 256), 256, smem_gemm>>>(
        hidden, Wq, Wk, Wv, 32, 40, qkv_p, HID_, QKVN_);

    // KV cache copy + RoPE/scatter
    copy_caches<<<2048, 256>>>((const float4*)ck, (const float4*)cv);
    {
        int total = B_ * Q_ * (H_ + 2 * KVH_) * D_;
        rope_scatter<<<(total + 255) / 256, 256>>>(cosp, sinp, sink);
    }

    // Attention
    size_t smem_attn = (size_t)(64 * KP + 64 * VP + 128 * SPD + 256) * sizeof(float);
    cudaFuncSetAttribute(attn_mma, cudaFuncAttributeMaxDynamicSharedMemorySize,
                         (int)smem_attn);
    attn_mma<<<dim3(Q_ / 128, H_, B_), 256, smem_attn>>>(mask);

    // Output projection -> d_out
    gemm_ldsm<<<dim3(HID_ / 128, M_ / 256), 256, smem_gemm>>>(
        attn_p, Wo, Wo, Wo, 1 << 20, 1 << 20, out, H_ * D_, HID_);
}

// round 12
// speedup vs baseline: 8.8320x; 1.0793x over previous
#include <cuda_runtime.h>
#include <math.h>
#include <stdint.h>

// Problem constants
#define B_    2
#define Q_    1024
#define H_    32
#define KVH_  8
#define D_    128
#define KV_   4096
#define HID_  4096
#define NREP_ (H_ / KVH_)
#define M_    (B_ * Q_)              // 2048
#define QKVN_ ((H_ + 2 * KVH_) * D_) // 6144

// Static device scratch (allocation-free rule)
__device__ float g_qkv[(size_t)M_ * QKVN_];            // [m][6144]
__device__ float g_q  [(size_t)B_ * H_  * Q_  * D_];   // tf32-rounded, pre-scaled
__device__ float g_k  [(size_t)B_ * KVH_ * KV_ * D_];  // tf32-rounded
__device__ float g_v  [(size_t)B_ * KVH_ * KV_ * D_];  // tf32-rounded
__device__ float g_attn[(size_t)M_ * H_ * D_];         // tf32-rounded
__device__ float g_hid [(size_t)M_ * HID_];            // tf32-rounded hidden
__device__ float g_w   [(size_t)QKVN_ * HID_];         // tf32 [Wq|Wk|Wv] rows
__device__ float g_wo  [(size_t)HID_ * (H_ * D_)];     // tf32 Wo

// ---------------------------------------------------------------------------
// helpers
// ---------------------------------------------------------------------------
__device__ __forceinline__ float tf32r(float x) {
    uint32_t u;
    asm("cvt.rna.tf32.f32 %0, %1;" : "=r"(u) : "f"(x));
    return __uint_as_float(u);
}

__device__ __forceinline__ void mma8(float c[4], const uint32_t a[4], const uint32_t b[2]) {
    asm volatile(
        "mma.sync.aligned.m16n8k8.row.col.f32.tf32.tf32.f32 "
        "{%0,%1,%2,%3}, {%4,%5,%6,%7}, {%8,%9}, {%0,%1,%2,%3};\n"
        : "+f"(c[0]), "+f"(c[1]), "+f"(c[2]), "+f"(c[3])
        : "r"(a[0]), "r"(a[1]), "r"(a[2]), "r"(a[3]), "r"(b[0]), "r"(b[1]));
}

__device__ __forceinline__ uint32_t smem_u32(const void* p) {
    return (uint32_t)__cvta_generic_to_shared(p);
}

__device__ __forceinline__ void ldsm4(uint32_t& r0, uint32_t& r1, uint32_t& r2,
                                      uint32_t& r3, uint32_t addr) {
    asm volatile("ldmatrix.sync.aligned.m8n8.x4.shared.b16 {%0,%1,%2,%3}, [%4];"
                 : "=r"(r0), "=r"(r1), "=r"(r2), "=r"(r3) : "r"(addr));
}

__device__ __forceinline__ void cpa16(uint32_t dst, const void* src) {
    asm volatile("cp.async.cg.shared.global [%0], [%1], 16;" :: "r"(dst), "l"(src));
}
__device__ __forceinline__ void cpa_commit() {
    asm volatile("cp.async.commit_group;" ::: "memory");
}
template <int N> __device__ __forceinline__ void cpa_wait() {
    asm volatile("cp.async.wait_group %0;" :: "n"(N) : "memory");
}

// ---------------------------------------------------------------------------
// elementwise tf32 rounding (fp32 -> tf32-valued fp32), float4 vectorized
// ---------------------------------------------------------------------------
__global__ void cvt_tf32_k(const float4* __restrict__ src, float4* __restrict__ dst,
                           int n4)
{
    int i = blockIdx.x * blockDim.x + threadIdx.x;
    if (i >= n4) return;
    float4 v = src[i];
    dst[i] = make_float4(tf32r(v.x), tf32r(v.y), tf32r(v.z), tf32r(v.w));
}

// ---------------------------------------------------------------------------
// TF32 GEMM, cp.async pipelined: C[m][n] = sum_k A[m][k]*W[n][k]
// A, W must already be tf32-rounded. Block 256x128, BK=32, 256 threads,
// 8 warps as 4x2 of 64x64 warp tiles. 4-deep smem ring, issue distance 2,
// ONE barrier per stage. smem pitch 36 floats (conflict-free STS/LDSM).
// ---------------------------------------------------------------------------
#define GP2 36
#define SA_ (256 * GP2)
#define SB_ (128 * GP2)
__global__ __launch_bounds__(256) void gemm_async(
    const float* __restrict__ A, const float* __restrict__ W,
    float* __restrict__ C, int K, int ldc)
{
    extern __shared__ float sm[];
    float* As = sm;                 // [4][256][GP2]
    float* Bs = sm + 4 * SA_;       // [4][128][GP2]

    const int tid = threadIdx.x, lane = tid & 31, wid = tid >> 5;
    const int wm = wid >> 1, wn = wid & 1;
    const int bm = blockIdx.y * 256, bn = blockIdx.x * 128;
    const int r8 = tid >> 3, cj = tid & 7;
    const float* Ap = A + (size_t)(bm + r8) * K + cj * 4;
    const float* Wp = W + (size_t)(bn + r8) * K + cj * 4;
    const uint32_t asb = smem_u32(As), bsb = smem_u32(Bs);
    const int lrow = lane & 15, lcw = (lane >> 4) << 2;

    float acc[4][8][4];
#pragma unroll
    for (int mt = 0; mt < 4; mt++)
#pragma unroll
        for (int nt = 0; nt < 8; nt++)
#pragma unroll
            for (int i = 0; i < 4; i++) acc[mt][nt][i] = 0.f;

    const int nst = K / 32;

#define G_ISSUE(s)                                                              \
    {                                                                           \
        const int bf_ = (s) & 3;                                                \
        const float* ap_ = Ap + (size_t)(s) * 32;                               \
        const float* wp_ = Wp + (size_t)(s) * 32;                               \
        uint32_t da_ = asb + (uint32_t)(bf_ * SA_ + r8 * GP2 + cj * 4) * 4;     \
        uint32_t db_ = bsb + (uint32_t)(bf_ * SB_ + r8 * GP2 + cj * 4) * 4;     \
        _Pragma("unroll")                                                       \
        for (int i_ = 0; i_ < 8; i_++)                                          \
            cpa16(da_ + (uint32_t)(i_ * 32 * GP2) * 4, ap_ + (size_t)i_ * 32 * K); \
        _Pragma("unroll")                                                       \
        for (int i_ = 0; i_ < 4; i_++)                                          \
            cpa16(db_ + (uint32_t)(i_ * 32 * GP2) * 4, wp_ + (size_t)i_ * 32 * K); \
        cpa_commit();                                                           \
    }

    G_ISSUE(0);
    G_ISSUE(1);

    for (int s = 0; s < nst; s++) {
        const int buf = s & 3;
        if (s + 2 < nst) G_ISSUE(s + 2);
        const int rem = nst - 1 - s;
        if (rem >= 2) cpa_wait<2>();
        else if (rem == 1) cpa_wait<1>();
        else cpa_wait<0>();
        __syncthreads();

        const uint32_t abase = asb + (uint32_t)(buf * SA_ + wm * 64 * GP2) * 4;
        const uint32_t bbase = bsb + (uint32_t)(buf * SB_ + wn * 64 * GP2) * 4;
#pragma unroll
        for (int ks = 0; ks < 4; ks++) {
            uint32_t af[4][4], bf[8][2];
#pragma unroll
            for (int mt = 0; mt < 4; mt++)
                ldsm4(af[mt][0], af[mt][1], af[mt][2], af[mt][3],
                      abase + (uint32_t)((mt * 16 + lrow) * GP2 + ks * 8 + lcw) * 4);
#pragma unroll
            for (int p = 0; p < 4; p++) {
                uint32_t r0, r1, r2, r3;
                ldsm4(r0, r1, r2, r3,
                      bbase + (uint32_t)((p * 16 + lrow) * GP2 + ks * 8 + lcw) * 4);
                bf[2 * p][0] = r0; bf[2 * p + 1][0] = r1;
                bf[2 * p][1] = r2; bf[2 * p + 1][1] = r3;
            }
#pragma unroll
            for (int mt = 0; mt < 4; mt++)
#pragma unroll
                for (int nt = 0; nt < 8; nt++) mma8(acc[mt][nt], af[mt], bf[nt]);
        }
    }

    const int g = lane >> 2, t = lane & 3;
#pragma unroll
    for (int mt = 0; mt < 4; mt++)
#pragma unroll
        for (int nt = 0; nt < 8; nt++) {
            int row = bm + wm * 64 + mt * 16 + g;
            int col = bn + wn * 64 + nt * 8 + 2 * t;
            *(float2*)(C + (size_t)row * ldc + col) =
                make_float2(acc[mt][nt][0], acc[mt][nt][1]);
            *(float2*)(C + (size_t)(row + 8) * ldc + col) =
                make_float2(acc[mt][nt][2], acc[mt][nt][3]);
        }
#undef G_ISSUE
}

// ---------------------------------------------------------------------------
// Copy KV caches into scratch, rounding to tf32 on the way
// ---------------------------------------------------------------------------
__global__ void copy_caches(const float4* __restrict__ ck, const float4* __restrict__ cv)
{
    const int n = B_ * KVH_ * KV_ * D_ / 4;
    float4* dk = (float4*)g_k;
    float4* dv = (float4*)g_v;
    for (int i = blockIdx.x * blockDim.x + threadIdx.x; i < n;
         i += gridDim.x * blockDim.x) {
        float4 a = ck[i];
        dk[i] = make_float4(tf32r(a.x), tf32r(a.y), tf32r(a.z), tf32r(a.w));
        float4 b = cv[i];
        dv[i] = make_float4(tf32r(b.x), tf32r(b.y), tf32r(b.z), tf32r(b.w));
    }
}

// ---------------------------------------------------------------------------
// RoPE + scatter; Q pre-scaled by 1/sqrt(D); all outputs tf32-rounded
// ---------------------------------------------------------------------------
__global__ void rope_scatter(const float* __restrict__ cosp,
                             const float* __restrict__ sinp,
                             const int*   __restrict__ sink)
{
    int idx = blockIdx.x * blockDim.x + threadIdx.x;
    const int total = B_ * Q_ * (H_ + 2 * KVH_) * D_;
    if (idx >= total) return;
    int d = idx & (D_ - 1);
    int t = idx >> 7;
    int head = t % (H_ + 2 * KVH_); t /= (H_ + 2 * KVH_);
    int q = t % Q_;
    int b = t / Q_;
    const float* row = g_qkv + (size_t)(b * Q_ + q) * QKVN_;

    if (head < H_ + KVH_) {
        float c = cosp[(size_t)(b * Q_ + q) * D_ + d];
        float s = sinp[(size_t)(b * Q_ + q) * D_ + d];
        int off = (head < H_) ? head * D_ : (H_ * D_ + (head - H_) * D_);
        float x  = row[off + d];
        float xp = (d < D_ / 2) ? row[off + d + D_ / 2] : row[off + d - D_ / 2];
        float r  = (d < D_ / 2) ? (x * c - xp * s) : (x * c + xp * s);
        if (head < H_) {
            g_q[((size_t)(b * H_ + head) * Q_ + q) * D_ + d] =
                tf32r(r * 0.08838834764831845f);
        } else {
            int kvh = head - H_;
            int sid = sink[q];
            g_k[((size_t)(b * KVH_ + kvh) * KV_ + sid) * D_ + d] = tf32r(r);
        }
    } else {
        int kvh = head - H_ - KVH_;
        int sid = sink[q];
        g_v[((size_t)(b * KVH_ + kvh) * KV_ + sid) * D_ + d] =
            tf32r(row[(H_ + KVH_) * D_ + kvh * D_ + d]);
    }
}

// ---------------------------------------------------------------------------
// Flash attention, TF32 mma + ldmatrix + cp.async double-buffered K/V.
// Block = 128 q-rows x one (b,h). 256 threads / 8 warps.
// S-phase: warp w owns q-rows [16w,16w+16). Softmax fully in registers
// (quad shuffles). P stored once (tf32) to sS for PV ldmatrix re-layout.
// P-phase: 4x2 warp grid, warp owns 32 q-rows x 64 d-cols.
// ---------------------------------------------------------------------------
#define KP 132
#define VP 136
#define SPD 68
__global__ __launch_bounds__(256, 1) void attn_mma(const float* __restrict__ mask)
{
    extern __shared__ float sm[];
    float* sK    = sm;                      // [2][64][KP]
    float* sV    = sK + 2 * 64 * KP;        // [2][64][VP]
    float* sS    = sV + 2 * 64 * VP;        // [128][SPD]
    float* scorr = sS + 128 * SPD;          // [128]
    float* slsum = scorr + 128;             // [128]

    const int tid = threadIdx.x, lane = tid & 31, w = tid >> 5;
    const int b = blockIdx.z, h = blockIdx.y, q0 = blockIdx.x * 128;
    const int kvh = h / NREP_;
    const int g = lane >> 2, t = lane & 3;
    const int lrow = lane & 15, lcw = (lane >> 4) << 2;
    const int pm = w >> 1, pn = w & 1;
    const int r0 = w * 16 + g;

    const uint32_t skb = smem_u32(sK), svb = smem_u32(sV), ssb = smem_u32(sS);

    const float* Kb = g_k + (size_t)(b * KVH_ + kvh) * KV_ * D_;
    const float* Vb = g_v + (size_t)(b * KVH_ + kvh) * KV_ * D_;
    const float* mbase = mask + ((size_t)b * Q_ + q0) * KV_;

    // cp.async producer mapping: thread covers rows lr+8i, 16B chunk lc4
    const int lr = tid >> 5, lc4 = (tid & 31) * 4;

#define KV_ISSUE(it_)                                                            \
    {                                                                            \
        const int bf_ = (it_) & 1;                                               \
        const float* Kg_ = Kb + (size_t)((it_) * 64) * D_;                       \
        const float* Vg_ = Vb + (size_t)((it_) * 64) * D_;                       \
        uint32_t dk_ = skb + (uint32_t)(bf_ * 64 * KP + lr * KP + lc4) * 4;      \
        uint32_t dv_ = svb + (uint32_t)(bf_ * 64 * VP + lr * VP + lc4) * 4;      \
        _Pragma("unroll")                                                        \
        for (int i_ = 0; i_ < 8; i_++) {                                         \
            cpa16(dk_ + (uint32_t)(i_ * 8 * KP) * 4,                             \
                  Kg_ + (size_t)(lr + 8 * i_) * D_ + lc4);                       \
            cpa16(dv_ + (uint32_t)(i_ * 8 * VP) * 4,                             \
                  Vg_ + (size_t)(lr + 8 * i_) * D_ + lc4);                       \
        }                                                                        \
        cpa_commit();                                                            \
    }

    KV_ISSUE(0);

    // preload Q fragments (g_q already tf32-rounded)
    const float* Qg = g_q + ((size_t)(b * H_ + h) * Q_ + q0 + w * 16) * D_;
    uint32_t qf[16][4];
#pragma unroll
    for (int ks = 0; ks < 16; ks++) {
        qf[ks][0] = __float_as_uint(Qg[(size_t)g * D_ + ks * 8 + t]);
        qf[ks][1] = __float_as_uint(Qg[(size_t)(g + 8) * D_ + ks * 8 + t]);
        qf[ks][2] = __float_as_uint(Qg[(size_t)g * D_ + ks * 8 + t + 4]);
        qf[ks][3] = __float_as_uint(Qg[(size_t)(g + 8) * D_ + ks * 8 + t + 4]);
    }

    float accO[2][8][4];
#pragma unroll
    for (int mq = 0; mq < 2; mq++)
#pragma unroll
        for (int nt = 0; nt < 8; nt++)
#pragma unroll
            for (int i = 0; i < 4; i++) accO[mq][nt][i] = 0.f;

    float m0 = -1e30f, m1 = -1e30f, l0 = 0.f, l1 = 0.f;

    const int NT = KV_ / 64;
    for (int it = 0; it < NT; it++) {
        const int j0 = it * 64;
        const int buf = it & 1;
        if (it > 0) __syncthreads();        // all readers of both bufs + sS done
        if (it + 1 < NT) { KV_ISSUE(it + 1); cpa_wait<1>(); }
        else cpa_wait<0>();
        __syncthreads();

        // ---- S = Q @ K^T (warp w: 16 rows x 64 cols), K-frags via ldmatrix ----
        const uint32_t kbase = skb + (uint32_t)(buf * 64 * KP) * 4;
        float sacc[8][4];
#pragma unroll
        for (int nt = 0; nt < 8; nt++)
#pragma unroll
            for (int i = 0; i < 4; i++) sacc[nt][i] = 0.f;
#pragma unroll
        for (int ks = 0; ks < 16; ks++) {
            uint32_t bf[8][2];
#pragma unroll
            for (int p = 0; p < 4; p++) {
                uint32_t r0w, r1w, r2w, r3w;
                ldsm4(r0w, r1w, r2w, r3w,
                      kbase + (uint32_t)((p * 16 + lrow) * KP + ks * 8 + lcw) * 4);
                bf[2 * p][0] = r0w; bf[2 * p + 1][0] = r1w;
                bf[2 * p][1] = r2w; bf[2 * p + 1][1] = r3w;
            }
#pragma unroll
            for (int nt = 0; nt < 8; nt++) mma8(sacc[nt], qf[ks], bf[nt]);
        }

        // ---- register softmax (rows r0, r0+8 per lane; quad owns a row) ----
        float mx0 = -1e30f, mx1 = -1e30f;
#pragma unroll
        for (int nt = 0; nt < 8; nt++) {
            float2 a = *(const float2*)(mbase + (size_t)r0 * KV_ + j0 + nt * 8 + 2 * t);
            float2 c = *(const float2*)(mbase + (size_t)(r0 + 8) * KV_ + j0 + nt * 8 + 2 * t);
            sacc[nt][0] += a.x; sacc[nt][1] += a.y;
            sacc[nt][2] += c.x; sacc[nt][3] += c.y;
            mx0 = fmaxf(mx0, fmaxf(sacc[nt][0], sacc[nt][1]));
            mx1 = fmaxf(mx1, fmaxf(sacc[nt][2], sacc[nt][3]));
        }
        mx0 = fmaxf(mx0, __shfl_xor_sync(0xffffffffu, mx0, 1));
        mx0 = fmaxf(mx0, __shfl_xor_sync(0xffffffffu, mx0, 2));
        mx1 = fmaxf(mx1, __shfl_xor_sync(0xffffffffu, mx1, 1));
        mx1 = fmaxf(mx1, __shfl_xor_sync(0xffffffffu, mx1, 2));
        float mn0 = fmaxf(m0, mx0), mn1 = fmaxf(m1, mx1);
        float ss0 = 0.f, ss1 = 0.f;
#pragma unroll
        for (int nt = 0; nt < 8; nt++) {
            float p00 = __expf(sacc[nt][0] - mn0), p01 = __expf(sacc[nt][1] - mn0);
            float p10 = __expf(sacc[nt][2] - mn1), p11 = __expf(sacc[nt][3] - mn1);
            ss0 += p00 + p01; ss1 += p10 + p11;
            *(float2*)(sS + r0 * SPD + nt * 8 + 2 * t) =
                make_float2(tf32r(p00), tf32r(p01));
            *(float2*)(sS + (r0 + 8) * SPD + nt * 8 + 2 * t) =
                make_float2(tf32r(p10), tf32r(p11));
        }
        ss0 += __shfl_xor_sync(0xffffffffu, ss0, 1);
        ss0 += __shfl_xor_sync(0xffffffffu, ss0, 2);
        ss1 += __shfl_xor_sync(0xffffffffu, ss1, 1);
        ss1 += __shfl_xor_sync(0xffffffffu, ss1, 2);
        float c0 = __expf(m0 - mn0), c1 = __expf(m1 - mn1);
        l0 = l0 * c0 + ss0; l1 = l1 * c1 + ss1;
        m0 = mn0; m1 = mn1;
        if (t == 0) {
            scorr[r0] = c0; scorr[r0 + 8] = c1;
            slsum[r0] = l0; slsum[r0 + 8] = l1;
        }
        __syncthreads();

        // ---- O = corr*O + P @ V  (warp: 32 q-rows x 64 d-cols) ----
        {
            const float* sVb = sV + buf * 64 * VP;
            float cA = scorr[pm * 32 + g],      cB = scorr[pm * 32 + 8 + g];
            float cC = scorr[pm * 32 + 16 + g], cD = scorr[pm * 32 + 24 + g];
#pragma unroll
            for (int nt = 0; nt < 8; nt++) {
                accO[0][nt][0] *= cA; accO[0][nt][1] *= cA;
                accO[0][nt][2] *= cB; accO[0][nt][3] *= cB;
                accO[1][nt][0] *= cC; accO[1][nt][1] *= cC;
                accO[1][nt][2] *= cD; accO[1][nt][3] *= cD;
            }
#pragma unroll
            for (int ks = 0; ks < 8; ks++) {
                uint32_t af[2][4];
#pragma unroll
                for (int mq = 0; mq < 2; mq++)
                    ldsm4(af[mq][0], af[mq][1], af[mq][2], af[mq][3],
                          ssb + (uint32_t)((pm * 32 + mq * 16 + lrow) * SPD
                                           + ks * 8 + lcw) * 4);
#pragma unroll
                for (int nt = 0; nt < 8; nt++) {
                    uint32_t bf[2];
                    const float* vp = sVb + (ks * 8 + t) * VP + pn * 64 + nt * 8 + g;
                    bf[0] = __float_as_uint(vp[0]);
                    bf[1] = __float_as_uint(vp[4 * VP]);
                    mma8(accO[0][nt], af[0], bf);
                    mma8(accO[1][nt], af[1], bf);
                }
            }
        }
    }
    __syncthreads();

    // ---- write O (tf32-rounded: consumed by Wo GEMM via cp.async) ----
#pragma unroll
    for (int mq = 0; mq < 2; mq++) {
        float i0 = 1.f / slsum[pm * 32 + mq * 16 + g];
        float i1 = 1.f / slsum[pm * 32 + mq * 16 + 8 + g];
        float* op  = g_attn + (size_t)(b * Q_ + q0 + pm * 32 + mq * 16 + g) * (H_ * D_)
                   + h * D_ + pn * 64;
        float* op8 = op + (size_t)8 * (H_ * D_);
#pragma unroll
        for (int nt = 0; nt < 8; nt++) {
            *(float2*)(op  + nt * 8 + 2 * t) =
                make_float2(tf32r(accO[mq][nt][0] * i0), tf32r(accO[mq][nt][1] * i0));
            *(float2*)(op8 + nt * 8 + 2 * t) =
                make_float2(tf32r(accO[mq][nt][2] * i1), tf32r(accO[mq][nt][3] * i1));
        }
    }
#undef KV_ISSUE
}

// ---------------------------------------------------------------------------
extern "C" void kernel_launch(void* const* d_in, const int* in_sizes, int n_in,
                              void* d_out, int out_size)
{
    const float* hidden = (const float*)d_in[0];
    const float* cosp   = (const float*)d_in[1];
    const float* sinp   = (const float*)d_in[2];
    const float* mask   = (const float*)d_in[3];
    const float* ck     = (const float*)d_in[4];
    const float* cv     = (const float*)d_in[5];
    const int*   sink   = (const int*)d_in[6];
    const float* Wq     = (const float*)d_in[7];
    const float* Wk     = (const float*)d_in[8];
    const float* Wv     = (const float*)d_in[9];
    const float* Wo     = (const float*)d_in[10];
    float* out = (float*)d_out;

    float *qkv_p = nullptr, *attn_p = nullptr, *hid_p = nullptr;
    float *w_p = nullptr, *wo_p = nullptr;
    cudaGetSymbolAddress((void**)&qkv_p, g_qkv);
    cudaGetSymbolAddress((void**)&attn_p, g_attn);
    cudaGetSymbolAddress((void**)&hid_p, g_hid);
    cudaGetSymbolAddress((void**)&w_p, g_w);
    cudaGetSymbolAddress((void**)&wo_p, g_wo);

    // Pre-round inputs to tf32 (bandwidth-bound; cvt is free here)
    {
        int n4h = M_ * HID_ / 4;
        cvt_tf32_k<<<(n4h + 255) / 256, 256>>>((const float4*)hidden, (float4*)hid_p, n4h);
        int n4q = H_ * D_ * HID_ / 4;
        cvt_tf32_k<<<(n4q + 255) / 256, 256>>>((const float4*)Wq, (float4*)w_p, n4q);
        int n4k = KVH_ * D_ * HID_ / 4;
        cvt_tf32_k<<<(n4k + 255) / 256, 256>>>((const float4*)Wk,
                                               (float4*)(w_p + (size_t)H_ * D_ * HID_), n4k);
        cvt_tf32_k<<<(n4k + 255) / 256, 256>>>((const float4*)Wv,
                                               (float4*)(w_p + (size_t)(H_ + KVH_) * D_ * HID_), n4k);
        int n4o = HID_ * H_ * D_ / 4;
        cvt_tf32_k<<<(n4o + 255) / 256, 256>>>((const float4*)Wo, (float4*)wo_p, n4o);
    }

    const int smem_gemm = 4 * (SA_ + SB_) * 4;   // 221184 B
    cudaFuncSetAttribute(gemm_async, cudaFuncAttributeMaxDynamicSharedMemorySize,
                         smem_gemm);

    // Fused QKV projection (W = [Wq|Wk|Wv] rows, pre-rounded)
    gemm_async<<<dim3(QKVN_ / 128, M_ / 256), 256, smem_gemm>>>(
        hid_p, w_p, qkv_p, HID_, QKVN_);

    // KV cache copy (tf32-rounded) + RoPE/scatter (tf32-rounded)
    copy_caches<<<2048, 256>>>((const float4*)ck, (const float4*)cv);
    {
        int total = B_ * Q_ * (H_ + 2 * KVH_) * D_;
        rope_scatter<<<(total + 255) / 256, 256>>>(cosp, sinp, sink);
    }

    // Attention
    size_t smem_attn = (size_t)(2 * 64 * KP + 2 * 64 * VP + 128 * SPD + 256) * sizeof(float);
    cudaFuncSetAttribute(attn_mma, cudaFuncAttributeMaxDynamicSharedMemorySize,
                         (int)smem_attn);
    attn_mma<<<dim3(Q_ / 128, H_, B_), 256, smem_attn>>>(mask);

    // Output projection -> d_out
    gemm_async<<<dim3((HID_) / 128, M_ / 256), 256, smem_gemm>>>(
        attn_p, wo_p, out, H_ * D_, HID_);
}

// round 13
// speedup vs baseline: 13.5600x; 1.5353x over previous
#include <cuda_runtime.h>
#include <cuda_fp16.h>
#include <math.h>
#include <stdint.h>

// Problem constants
#define B_    2
#define Q_    1024
#define H_    32
#define KVH_  8
#define D_    128
#define KV_   4096
#define HID_  4096
#define NREP_ (H_ / KVH_)
#define M_    (B_ * Q_)              // 2048
#define QKVN_ ((H_ + 2 * KVH_) * D_) // 6144

// Static device scratch (allocation-free rule)
__device__ float  g_qkv [(size_t)M_ * QKVN_];            // fp32 GEMM out
__device__ __half g_hidh[(size_t)M_ * HID_];             // fp16 hidden
__device__ __half g_wh  [(size_t)QKVN_ * HID_];          // fp16 [Wq|Wk|Wv]
__device__ __half g_woh [(size_t)HID_ * (H_ * D_)];      // fp16 Wo
__device__ __half g_qh  [(size_t)B_ * H_  * Q_  * D_];   // fp16 Q (pre-scaled)
__device__ __half g_kh  [(size_t)B_ * KVH_ * KV_ * D_];  // fp16 K cache
__device__ __half g_vh  [(size_t)B_ * KVH_ * KV_ * D_];  // fp16 V cache
__device__ __half g_attnh[(size_t)M_ * H_ * D_];         // fp16 attn out

// ---------------------------------------------------------------------------
// helpers
// ---------------------------------------------------------------------------
__device__ __forceinline__ void mma16(float c[4], const uint32_t a[4], const uint32_t b[2]) {
    asm volatile(
        "mma.sync.aligned.m16n8k16.row.col.f32.f16.f16.f32 "
        "{%0,%1,%2,%3}, {%4,%5,%6,%7}, {%8,%9}, {%0,%1,%2,%3};\n"
        : "+f"(c[0]), "+f"(c[1]), "+f"(c[2]), "+f"(c[3])
        : "r"(a[0]), "r"(a[1]), "r"(a[2]), "r"(a[3]), "r"(b[0]), "r"(b[1]));
}

__device__ __forceinline__ uint32_t smem_u32(const void* p) {
    return (uint32_t)__cvta_generic_to_shared(p);
}

__device__ __forceinline__ void ldsm4(uint32_t& r0, uint32_t& r1, uint32_t& r2,
                                      uint32_t& r3, uint32_t addr) {
    asm volatile("ldmatrix.sync.aligned.m8n8.x4.shared.b16 {%0,%1,%2,%3}, [%4];"
                 : "=r"(r0), "=r"(r1), "=r"(r2), "=r"(r3) : "r"(addr));
}
__device__ __forceinline__ void ldsm4t(uint32_t& r0, uint32_t& r1, uint32_t& r2,
                                       uint32_t& r3, uint32_t addr) {
    asm volatile("ldmatrix.sync.aligned.m8n8.x4.trans.shared.b16 {%0,%1,%2,%3}, [%4];"
                 : "=r"(r0), "=r"(r1), "=r"(r2), "=r"(r3) : "r"(addr));
}

__device__ __forceinline__ void cpa16(uint32_t dst, const void* src) {
    asm volatile("cp.async.cg.shared.global [%0], [%1], 16;" :: "r"(dst), "l"(src));
}
__device__ __forceinline__ void cpa_commit() {
    asm volatile("cp.async.commit_group;" ::: "memory");
}
template <int N> __device__ __forceinline__ void cpa_wait() {
    asm volatile("cp.async.wait_group %0;" :: "n"(N) : "memory");
}

// ---------------------------------------------------------------------------
// fp32 -> fp16 conversion (bandwidth-bound)
// ---------------------------------------------------------------------------
__global__ void cvt_half_k(const float4* __restrict__ src, __half2* __restrict__ dst,
                           int n4)
{
    int i = blockIdx.x * blockDim.x + threadIdx.x;
    if (i >= n4) return;
    float4 v = src[i];
    dst[2 * i]     = __floats2half2_rn(v.x, v.y);
    dst[2 * i + 1] = __floats2half2_rn(v.z, v.w);
}

// ---------------------------------------------------------------------------
// fp16 GEMM, cp.async pipelined: C[m][n] = sum_k A[m][k]*W[n][k]  (fp32 accum)
// Block 256x128, BK=32 halfs (64B rows), 256 threads, 8 warps (4x2, 64x64).
// 4-stage ring, issue distance 2, one barrier per stage.
// smem row pitch 80B (conflict-free STS16 / ldmatrix).
// ---------------------------------------------------------------------------
#define APB 80                 // bytes per A/B smem row
#define SAB (256 * APB)        // 20480 B per A stage
#define SBB (128 * APB)        // 10240 B per B stage
__global__ __launch_bounds__(256) void gemm_h(
    const __half* __restrict__ A, const __half* __restrict__ W,
    float* __restrict__ C, int K, int ldc)
{
    extern __shared__ char sm[];
    const uint32_t asb = smem_u32(sm);
    const uint32_t bsb = asb + 4 * SAB;

    const int tid = threadIdx.x, lane = tid & 31, wid = tid >> 5;
    const int wm = wid >> 1, wn = wid & 1;
    const int bm = blockIdx.y * 256, bn = blockIdx.x * 128;
    const int lrow = lane & 15;
    const uint32_t hi16 = (uint32_t)((lane >> 4) << 4);

    const int arow = tid >> 2, acol = tid & 3;       // 16B chunk within 64B row
    const __half* Ap = A + (size_t)(bm + arow) * K + acol * 8;
    const __half* Wp = W + (size_t)(bn + arow) * K + acol * 8;

    float acc[4][8][4];
#pragma unroll
    for (int mt = 0; mt < 4; mt++)
#pragma unroll
        for (int nt = 0; nt < 8; nt++)
#pragma unroll
            for (int i = 0; i < 4; i++) acc[mt][nt][i] = 0.f;

    const int nst = K / 32;

#define G_ISSUE(s)                                                               \
    {                                                                            \
        const int bf_ = (s) & 3;                                                 \
        const __half* ap_ = Ap + (size_t)(s) * 32;                               \
        const __half* wp_ = Wp + (size_t)(s) * 32;                               \
        uint32_t da_ = asb + (uint32_t)(bf_ * SAB + arow * APB + acol * 16);     \
        uint32_t db_ = bsb + (uint32_t)(bf_ * SBB + arow * APB + acol * 16);     \
        _Pragma("unroll")                                                        \
        for (int i_ = 0; i_ < 4; i_++)                                           \
            cpa16(da_ + (uint32_t)(i_ * 64 * APB), ap_ + (size_t)i_ * 64 * K);   \
        _Pragma("unroll")                                                        \
        for (int i_ = 0; i_ < 2; i_++)                                           \
            cpa16(db_ + (uint32_t)(i_ * 64 * APB), wp_ + (size_t)i_ * 64 * K);   \
        cpa_commit();                                                            \
    }

    G_ISSUE(0);
    G_ISSUE(1);

    for (int s = 0; s < nst; s++) {
        const int buf = s & 3;
        if (s + 2 < nst) G_ISSUE(s + 2);
        const int rem = nst - 1 - s;
        if (rem >= 2) cpa_wait<2>();
        else if (rem == 1) cpa_wait<1>();
        else cpa_wait<0>();
        __syncthreads();

        const uint32_t abase = asb + (uint32_t)(buf * SAB + wm * 64 * APB);
        const uint32_t bbase = bsb + (uint32_t)(buf * SBB + wn * 64 * APB);
#pragma unroll
        for (int ks = 0; ks < 2; ks++) {
            uint32_t af[4][4], bf[8][2];
#pragma unroll
            for (int mt = 0; mt < 4; mt++)
                ldsm4(af[mt][0], af[mt][1], af[mt][2], af[mt][3],
                      abase + (uint32_t)((mt * 16 + lrow) * APB + ks * 32) + hi16);
#pragma unroll
            for (int p = 0; p < 4; p++) {
                uint32_t r0, r1, r2, r3;
                ldsm4(r0, r1, r2, r3,
                      bbase + (uint32_t)((p * 16 + lrow) * APB + ks * 32) + hi16);
                bf[2 * p][0] = r0; bf[2 * p + 1][0] = r1;
                bf[2 * p][1] = r2; bf[2 * p + 1][1] = r3;
            }
#pragma unroll
            for (int mt = 0; mt < 4; mt++)
#pragma unroll
                for (int nt = 0; nt < 8; nt++) mma16(acc[mt][nt], af[mt], bf[nt]);
        }
    }

    const int g = lane >> 2, t = lane & 3;
#pragma unroll
    for (int mt = 0; mt < 4; mt++)
#pragma unroll
        for (int nt = 0; nt < 8; nt++) {
            int row = bm + wm * 64 + mt * 16 + g;
            int col = bn + wn * 64 + nt * 8 + 2 * t;
            *(float2*)(C + (size_t)row * ldc + col) =
                make_float2(acc[mt][nt][0], acc[mt][nt][1]);
            *(float2*)(C + (size_t)(row + 8) * ldc + col) =
                make_float2(acc[mt][nt][2], acc[mt][nt][3]);
        }
#undef G_ISSUE
}

// ---------------------------------------------------------------------------
// Copy KV caches into fp16 scratch
// ---------------------------------------------------------------------------
__global__ void copy_caches(const float4* __restrict__ ck, const float4* __restrict__ cv)
{
    const int n = B_ * KVH_ * KV_ * D_ / 4;
    __half2* dk = (__half2*)g_kh;
    __half2* dv = (__half2*)g_vh;
    for (int i = blockIdx.x * blockDim.x + threadIdx.x; i < n;
         i += gridDim.x * blockDim.x) {
        float4 a = ck[i];
        dk[2 * i]     = __floats2half2_rn(a.x, a.y);
        dk[2 * i + 1] = __floats2half2_rn(a.z, a.w);
        float4 b = cv[i];
        dv[2 * i]     = __floats2half2_rn(b.x, b.y);
        dv[2 * i + 1] = __floats2half2_rn(b.z, b.w);
    }
}

// ---------------------------------------------------------------------------
// RoPE + scatter; Q pre-scaled by 1/sqrt(D); fp16 outputs
// ---------------------------------------------------------------------------
__global__ void rope_scatter(const float* __restrict__ cosp,
                             const float* __restrict__ sinp,
                             const int*   __restrict__ sink)
{
    int idx = blockIdx.x * blockDim.x + threadIdx.x;
    const int total = B_ * Q_ * (H_ + 2 * KVH_) * D_;
    if (idx >= total) return;
    int d = idx & (D_ - 1);
    int t = idx >> 7;
    int head = t % (H_ + 2 * KVH_); t /= (H_ + 2 * KVH_);
    int q = t % Q_;
    int b = t / Q_;
    const float* row = g_qkv + (size_t)(b * Q_ + q) * QKVN_;

    if (head < H_ + KVH_) {
        float c = cosp[(size_t)(b * Q_ + q) * D_ + d];
        float s = sinp[(size_t)(b * Q_ + q) * D_ + d];
        int off = (head < H_) ? head * D_ : (H_ * D_ + (head - H_) * D_);
        float x  = row[off + d];
        float xp = (d < D_ / 2) ? row[off + d + D_ / 2] : row[off + d - D_ / 2];
        float r  = (d < D_ / 2) ? (x * c - xp * s) : (x * c + xp * s);
        if (head < H_) {
            g_qh[((size_t)(b * H_ + head) * Q_ + q) * D_ + d] =
                __float2half_rn(r * 0.08838834764831845f);
        } else {
            int kvh = head - H_;
            int sid = sink[q];
            g_kh[((size_t)(b * KVH_ + kvh) * KV_ + sid) * D_ + d] = __float2half_rn(r);
        }
    } else {
        int kvh = head - H_ - KVH_;
        int sid = sink[q];
        g_vh[((size_t)(b * KVH_ + kvh) * KV_ + sid) * D_ + d] =
            __float2half_rn(row[(H_ + KVH_) * D_ + kvh * D_ + d]);
    }
}

// ---------------------------------------------------------------------------
// Flash attention, fp16 mma (fp32 accum/softmax), cp.async double-buffered.
// Block = 128 q-rows x one (b,h). 256 threads / 8 warps.
// S-phase: warp w owns q-rows [16w,16w+16); mask preloaded into accumulator.
// Softmax in registers. P stored fp16 to sS. PV: 4x2 warp grid, V fragments
// via ldmatrix.trans from row-major V (no transpose copies anywhere).
// smem (bytes): K tile row pitch 272, S row pitch 144.
// ---------------------------------------------------------------------------
#define KTB 17408              // 64 * 272 bytes per K/V tile
#define SPB 144                // sS row pitch bytes (72 halfs)
#define OFF_K  0
#define OFF_V  (2 * KTB)
#define OFF_S  (4 * KTB)
#define OFF_C  (OFF_S + 128 * SPB)
#define OFF_L  (OFF_C + 512)
#define ATTN_SMEM (OFF_L + 512)
__global__ __launch_bounds__(256, 1) void attn_h(const float* __restrict__ mask)
{
    extern __shared__ char sm[];
    const uint32_t smb = smem_u32(sm);
    __half* sSh   = (__half*)(sm + OFF_S);
    float*  scorr = (float*)(sm + OFF_C);
    float*  slsum = (float*)(sm + OFF_L);

    const int tid = threadIdx.x, lane = tid & 31, w = tid >> 5;
    const int b = blockIdx.z, h = blockIdx.y, q0 = blockIdx.x * 128;
    const int kvh = h / NREP_;
    const int g = lane >> 2, t = lane & 3;
    const int lrow = lane & 15;
    const uint32_t hi16 = (uint32_t)((lane >> 4) << 4);
    const int pm = w >> 1, pn = w & 1;
    const int r0 = w * 16 + g;

    const __half* Kb = g_kh + (size_t)(b * KVH_ + kvh) * KV_ * D_;
    const __half* Vb = g_vh + (size_t)(b * KVH_ + kvh) * KV_ * D_;
    const float* mbase = mask + ((size_t)b * Q_ + q0) * KV_;

    const int crow = tid >> 4, ccol = tid & 15;   // cp.async mapping

#define KV_ISSUE(it_)                                                            \
    {                                                                            \
        const int bf_ = (it_) & 1;                                               \
        const __half* Kg_ = Kb + (size_t)((it_) * 64) * D_;                      \
        const __half* Vg_ = Vb + (size_t)((it_) * 64) * D_;                      \
        uint32_t dk_ = smb + (uint32_t)(OFF_K + bf_ * KTB + crow * 272 + ccol * 16); \
        uint32_t dv_ = smb + (uint32_t)(OFF_V + bf_ * KTB + crow * 272 + ccol * 16); \
        _Pragma("unroll")                                                        \
        for (int i_ = 0; i_ < 4; i_++) {                                         \
            cpa16(dk_ + (uint32_t)(i_ * 16 * 272),                               \
                  Kg_ + (size_t)(crow + 16 * i_) * D_ + ccol * 8);               \
            cpa16(dv_ + (uint32_t)(i_ * 16 * 272),                               \
                  Vg_ + (size_t)(crow + 16 * i_) * D_ + ccol * 8);               \
        }                                                                        \
        cpa_commit();                                                            \
    }

    KV_ISSUE(0);

    // preload Q fragments (fp16): 8 k16-steps
    const __half* Qg = g_qh + ((size_t)(b * H_ + h) * Q_ + q0 + w * 16) * D_;
    uint32_t qf[8][4];
#pragma unroll
    for (int ks = 0; ks < 8; ks++) {
        const __half* qp = Qg + (size_t)g * D_ + ks * 16 + 2 * t;
        qf[ks][0] = *(const uint32_t*)qp;
        qf[ks][1] = *(const uint32_t*)(qp + (size_t)8 * D_);
        qf[ks][2] = *(const uint32_t*)(qp + 8);
        qf[ks][3] = *(const uint32_t*)(qp + (size_t)8 * D_ + 8);
    }

    float accO[2][8][4];
#pragma unroll
    for (int mq = 0; mq < 2; mq++)
#pragma unroll
        for (int nt = 0; nt < 8; nt++)
#pragma unroll
            for (int i = 0; i < 4; i++) accO[mq][nt][i] = 0.f;

    float m0 = -1e30f, m1 = -1e30f, l0 = 0.f, l1 = 0.f;

    const int NT = KV_ / 64;
    for (int it = 0; it < NT; it++) {
        const int j0 = it * 64;
        const int buf = it & 1;
        if (it > 0) __syncthreads();
        if (it + 1 < NT) { KV_ISSUE(it + 1); cpa_wait<1>(); }
        else cpa_wait<0>();
        __syncthreads();

        // ---- S = Q @ K^T + mask (mask preloaded into accumulators) ----
        float sacc[8][4];
#pragma unroll
        for (int nt = 0; nt < 8; nt++) {
            *(float2*)&sacc[nt][0] =
                *(const float2*)(mbase + (size_t)r0 * KV_ + j0 + nt * 8 + 2 * t);
            *(float2*)&sacc[nt][2] =
                *(const float2*)(mbase + (size_t)(r0 + 8) * KV_ + j0 + nt * 8 + 2 * t);
        }
        const uint32_t kbase = smb + (uint32_t)(OFF_K + buf * KTB);
#pragma unroll
        for (int ks = 0; ks < 8; ks++) {
            uint32_t bf[8][2];
#pragma unroll
            for (int p = 0; p < 4; p++) {
                uint32_t r0w, r1w, r2w, r3w;
                ldsm4(r0w, r1w, r2w, r3w,
                      kbase + (uint32_t)((p * 16 + lrow) * 272 + ks * 32) + hi16);
                bf[2 * p][0] = r0w; bf[2 * p + 1][0] = r1w;
                bf[2 * p][1] = r2w; bf[2 * p + 1][1] = r3w;
            }
#pragma unroll
            for (int nt = 0; nt < 8; nt++) mma16(sacc[nt], qf[ks], bf[nt]);
        }

        // ---- register softmax (rows r0, r0+8; quad owns a row) ----
        float mx0 = -1e30f, mx1 = -1e30f;
#pragma unroll
        for (int nt = 0; nt < 8; nt++) {
            mx0 = fmaxf(mx0, fmaxf(sacc[nt][0], sacc[nt][1]));
            mx1 = fmaxf(mx1, fmaxf(sacc[nt][2], sacc[nt][3]));
        }
        mx0 = fmaxf(mx0, __shfl_xor_sync(0xffffffffu, mx0, 1));
        mx0 = fmaxf(mx0, __shfl_xor_sync(0xffffffffu, mx0, 2));
        mx1 = fmaxf(mx1, __shfl_xor_sync(0xffffffffu, mx1, 1));
        mx1 = fmaxf(mx1, __shfl_xor_sync(0xffffffffu, mx1, 2));
        float mn0 = fmaxf(m0, mx0), mn1 = fmaxf(m1, mx1);
        float ss0 = 0.f, ss1 = 0.f;
#pragma unroll
        for (int nt = 0; nt < 8; nt++) {
            float p00 = __expf(sacc[nt][0] - mn0), p01 = __expf(sacc[nt][1] - mn0);
            float p10 = __expf(sacc[nt][2] - mn1), p11 = __expf(sacc[nt][3] - mn1);
            ss0 += p00 + p01; ss1 += p10 + p11;
            *(__half2*)(sSh + (size_t)r0 * 72 + nt * 8 + 2 * t) =
                __floats2half2_rn(p00, p01);
            *(__half2*)(sSh + (size_t)(r0 + 8) * 72 + nt * 8 + 2 * t) =
                __floats2half2_rn(p10, p11);
        }
        ss0 += __shfl_xor_sync(0xffffffffu, ss0, 1);
        ss0 += __shfl_xor_sync(0xffffffffu, ss0, 2);
        ss1 += __shfl_xor_sync(0xffffffffu, ss1, 1);
        ss1 += __shfl_xor_sync(0xffffffffu, ss1, 2);
        float c0 = __expf(m0 - mn0), c1 = __expf(m1 - mn1);
        l0 = l0 * c0 + ss0; l1 = l1 * c1 + ss1;
        m0 = mn0; m1 = mn1;
        if (t == 0) {
            scorr[r0] = c0; scorr[r0 + 8] = c1;
            slsum[r0] = l0; slsum[r0 + 8] = l1;
        }
        __syncthreads();

        // ---- O = corr*O + P @ V  (warp: 32 q-rows x 64 d-cols) ----
        {
            const uint32_t vbase = smb + (uint32_t)(OFF_V + buf * KTB);
            const uint32_t sbase = smb + (uint32_t)OFF_S;
            float cA = scorr[pm * 32 + g],      cB = scorr[pm * 32 + 8 + g];
            float cC = scorr[pm * 32 + 16 + g], cD = scorr[pm * 32 + 24 + g];
#pragma unroll
            for (int nt = 0; nt < 8; nt++) {
                accO[0][nt][0] *= cA; accO[0][nt][1] *= cA;
                accO[0][nt][2] *= cB; accO[0][nt][3] *= cB;
                accO[1][nt][0] *= cC; accO[1][nt][1] *= cC;
                accO[1][nt][2] *= cD; accO[1][nt][3] *= cD;
            }
#pragma unroll
            for (int ks = 0; ks < 4; ks++) {      // k16 chunks over 64 kv
                uint32_t af[2][4], bf[8][2];
#pragma unroll
                for (int mq = 0; mq < 2; mq++)
                    ldsm4(af[mq][0], af[mq][1], af[mq][2], af[mq][3],
                          sbase + (uint32_t)((pm * 32 + mq * 16 + lrow) * SPB
                                             + ks * 32) + hi16);
#pragma unroll
                for (int p = 0; p < 4; p++) {     // 16 d-cols per trans-ldsm
                    uint32_t r0w, r1w, r2w, r3w;
                    ldsm4t(r0w, r1w, r2w, r3w,
                           vbase + (uint32_t)((ks * 16 + lrow) * 272
                                              + (pn * 64 + p * 16) * 2) + hi16);
                    bf[2 * p][0] = r0w; bf[2 * p][1] = r1w;
                    bf[2 * p + 1][0] = r2w; bf[2 * p + 1][1] = r3w;
                }
#pragma unroll
                for (int nt = 0; nt < 8; nt++) {
                    mma16(accO[0][nt], af[0], bf[nt]);
                    mma16(accO[1][nt], af[1], bf[nt]);
                }
            }
        }
    }
    __syncthreads();

    // ---- write O (fp16, consumed by Wo GEMM) ----
#pragma unroll
    for (int mq = 0; mq < 2; mq++) {
        float i0 = 1.f / slsum[pm * 32 + mq * 16 + g];
        float i1 = 1.f / slsum[pm * 32 + mq * 16 + 8 + g];
        __half* op  = g_attnh + (size_t)(b * Q_ + q0 + pm * 32 + mq * 16 + g) * (H_ * D_)
                    + h * D_ + pn * 64;
        __half* op8 = op + (size_t)8 * (H_ * D_);
#pragma unroll
        for (int nt = 0; nt < 8; nt++) {
            *(__half2*)(op  + nt * 8 + 2 * t) =
                __floats2half2_rn(accO[mq][nt][0] * i0, accO[mq][nt][1] * i0);
            *(__half2*)(op8 + nt * 8 + 2 * t) =
                __floats2half2_rn(accO[mq][nt][2] * i1, accO[mq][nt][3] * i1);
        }
    }
#undef KV_ISSUE
}

// ---------------------------------------------------------------------------
extern "C" void kernel_launch(void* const* d_in, const int* in_sizes, int n_in,
                              void* d_out, int out_size)
{
    const float* hidden = (const float*)d_in[0];
    const float* cosp   = (const float*)d_in[1];
    const float* sinp   = (const float*)d_in[2];
    const float* mask   = (const float*)d_in[3];
    const float* ck     = (const float*)d_in[4];
    const float* cv     = (const float*)d_in[5];
    const int*   sink   = (const int*)d_in[6];
    const float* Wq     = (const float*)d_in[7];
    const float* Wk     = (const float*)d_in[8];
    const float* Wv     = (const float*)d_in[9];
    const float* Wo     = (const float*)d_in[10];
    float* out = (float*)d_out;

    float  *qkv_p = nullptr;
    __half *hidh_p = nullptr, *wh_p = nullptr, *woh_p = nullptr, *attnh_p = nullptr;
    cudaGetSymbolAddress((void**)&qkv_p, g_qkv);
    cudaGetSymbolAddress((void**)&hidh_p, g_hidh);
    cudaGetSymbolAddress((void**)&wh_p, g_wh);
    cudaGetSymbolAddress((void**)&woh_p, g_woh);
    cudaGetSymbolAddress((void**)&attnh_p, g_attnh);

    // fp32 -> fp16 conversions (bandwidth-bound)
    {
        int n4h = M_ * HID_ / 4;
        cvt_half_k<<<(n4h + 255) / 256, 256>>>((const float4*)hidden, (__half2*)hidh_p, n4h);
        int n4q = H_ * D_ * HID_ / 4;
        cvt_half_k<<<(n4q + 255) / 256, 256>>>((const float4*)Wq, (__half2*)wh_p, n4q);
        int n4k = KVH_ * D_ * HID_ / 4;
        cvt_half_k<<<(n4k + 255) / 256, 256>>>((const float4*)Wk,
            (__half2*)(wh_p + (size_t)H_ * D_ * HID_), n4k);
        cvt_half_k<<<(n4k + 255) / 256, 256>>>((const float4*)Wv,
            (__half2*)(wh_p + (size_t)(H_ + KVH_) * D_ * HID_), n4k);
        int n4o = HID_ * H_ * D_ / 4;
        cvt_half_k<<<(n4o + 255) / 256, 256>>>((const float4*)Wo, (__half2*)woh_p, n4o);
    }

    const int smem_gemm = 4 * (SAB + SBB);   // 122880 B
    cudaFuncSetAttribute(gemm_h, cudaFuncAttributeMaxDynamicSharedMemorySize, smem_gemm);

    // Fused QKV projection
    gemm_h<<<dim3(QKVN_ / 128, M_ / 256), 256, smem_gemm>>>(
        hidh_p, wh_p, qkv_p, HID_, QKVN_);

    // KV cache copy (fp16) + RoPE/scatter (fp16)
    copy_caches<<<2048, 256>>>((const float4*)ck, (const float4*)cv);
    {
        int total = B_ * Q_ * (H_ + 2 * KVH_) * D_;
        rope_scatter<<<(total + 255) / 256, 256>>>(cosp, sinp, sink);
    }

    // Attention
    cudaFuncSetAttribute(attn_h, cudaFuncAttributeMaxDynamicSharedMemorySize, ATTN_SMEM);
    attn_h<<<dim3(Q_ / 128, H_, B_), 256, ATTN_SMEM>>>(mask);

    // Output projection -> d_out
    gemm_h<<<dim3(HID_ / 128, M_ / 256), 256, smem_gemm>>>(
        attnh_p, woh_p, out, H_ * D_, HID_);
}

// round 16
// speedup vs baseline: 15.2597x; 1.1253x over previous
#include <cuda_runtime.h>
#include <cuda_fp16.h>
#include <math.h>
#include <stdint.h>

// Problem constants
#define B_    2
#define Q_    1024
#define H_    32
#define KVH_  8
#define D_    128
#define KV_   4096
#define HID_  4096
#define NREP_ (H_ / KVH_)
#define M_    (B_ * Q_)              // 2048
#define QKVN_ ((H_ + 2 * KVH_) * D_) // 6144

// Static device scratch (allocation-free rule)
__device__ float  g_qkv [(size_t)M_ * QKVN_];            // fp32 GEMM out
__device__ __half g_hidh[(size_t)M_ * HID_];             // fp16 hidden
__device__ __half g_wh  [(size_t)QKVN_ * HID_];          // fp16 [Wq|Wk|Wv]
__device__ __half g_woh [(size_t)HID_ * (H_ * D_)];      // fp16 Wo
__device__ __half g_qh  [(size_t)B_ * H_  * Q_  * D_];   // fp16 Q (pre-scaled)
__device__ __half g_kh  [(size_t)B_ * KVH_ * KV_ * D_];  // fp16 K cache
__device__ __half g_vh  [(size_t)B_ * KVH_ * KV_ * D_];  // fp16 V cache
__device__ __half g_attnh[(size_t)M_ * H_ * D_];         // fp16 attn out
__device__ __half g_mh  [(size_t)B_ * Q_ * KV_];         // fp16 mask (clamped)

// ---------------------------------------------------------------------------
// helpers
// ---------------------------------------------------------------------------
__device__ __forceinline__ void mma16(float c[4], const uint32_t a[4], const uint32_t b[2]) {
    asm volatile(
        "mma.sync.aligned.m16n8k16.row.col.f32.f16.f16.f32 "
        "{%0,%1,%2,%3}, {%4,%5,%6,%7}, {%8,%9}, {%0,%1,%2,%3};\n"
        : "+f"(c[0]), "+f"(c[1]), "+f"(c[2]), "+f"(c[3])
        : "r"(a[0]), "r"(a[1]), "r"(a[2]), "r"(a[3]), "r"(b[0]), "r"(b[1]));
}

// pack two fp32 into one fp16x2 register (rn)
__device__ __forceinline__ uint32_t pack_h2(float lo, float hi) {
    uint32_t r;
    asm("cvt.rn.f16x2.f32 %0, %1, %2;" : "=r"(r) : "f"(hi), "f"(lo));
    return r;
}

__device__ __forceinline__ uint32_t smem_u32(const void* p) {
    return (uint32_t)__cvta_generic_to_shared(p);
}

__device__ __forceinline__ void ldsm4(uint32_t& r0, uint32_t& r1, uint32_t& r2,
                                      uint32_t& r3, uint32_t addr) {
    asm volatile("ldmatrix.sync.aligned.m8n8.x4.shared.b16 {%0,%1,%2,%3}, [%4];"
                 : "=r"(r0), "=r"(r1), "=r"(r2), "=r"(r3) : "r"(addr));
}
__device__ __forceinline__ void ldsm4t(uint32_t& r0, uint32_t& r1, uint32_t& r2,
                                       uint32_t& r3, uint32_t addr) {
    asm volatile("ldmatrix.sync.aligned.m8n8.x4.trans.shared.b16 {%0,%1,%2,%3}, [%4];"
                 : "=r"(r0), "=r"(r1), "=r"(r2), "=r"(r3) : "r"(addr));
}

__device__ __forceinline__ void cpa16(uint32_t dst, const void* src) {
    asm volatile("cp.async.cg.shared.global [%0], [%1], 16;" :: "r"(dst), "l"(src));
}
__device__ __forceinline__ void cpa_commit() {
    asm volatile("cp.async.commit_group;" ::: "memory");
}
template <int N> __device__ __forceinline__ void cpa_wait() {
    asm volatile("cp.async.wait_group %0;" :: "n"(N) : "memory");
}

// ---------------------------------------------------------------------------
// fp32 -> fp16 conversions (bandwidth-bound)
// ---------------------------------------------------------------------------
__global__ void cvt_half_k(const float4* __restrict__ src, __half2* __restrict__ dst,
                           int n4)
{
    int i = blockIdx.x * blockDim.x + threadIdx.x;
    if (i >= n4) return;
    float4 v = src[i];
    dst[2 * i]     = __floats2half2_rn(v.x, v.y);
    dst[2 * i + 1] = __floats2half2_rn(v.z, v.w);
}

// mask: clamp to finite fp16 range so -1e9-style masks don't become -inf
__global__ void cvt_mask_k(const float4* __restrict__ src, __half2* __restrict__ dst,
                           int n4)
{
    int i = blockIdx.x * blockDim.x + threadIdx.x;
    if (i >= n4) return;
    float4 v = src[i];
    v.x = fmaxf(v.x, -60000.f); v.y = fmaxf(v.y, -60000.f);
    v.z = fmaxf(v.z, -60000.f); v.w = fmaxf(v.w, -60000.f);
    dst[2 * i]     = __floats2half2_rn(v.x, v.y);
    dst[2 * i + 1] = __floats2half2_rn(v.z, v.w);
}

// ---------------------------------------------------------------------------
// fp16 GEMM, cp.async pipelined (unchanged from R13 passing version)
// ---------------------------------------------------------------------------
#define APB 80
#define SAB (256 * APB)
#define SBB (128 * APB)
__global__ __launch_bounds__(256) void gemm_h(
    const __half* __restrict__ A, const __half* __restrict__ W,
    float* __restrict__ C, int K, int ldc)
{
    extern __shared__ char sm[];
    const uint32_t asb = smem_u32(sm);
    const uint32_t bsb = asb + 4 * SAB;

    const int tid = threadIdx.x, lane = tid & 31, wid = tid >> 5;
    const int wm = wid >> 1, wn = wid & 1;
    const int bm = blockIdx.y * 256, bn = blockIdx.x * 128;
    const int lrow = lane & 15;
    const uint32_t hi16 = (uint32_t)((lane >> 4) << 4);

    const int arow = tid >> 2, acol = tid & 3;
    const __half* Ap = A + (size_t)(bm + arow) * K + acol * 8;
    const __half* Wp = W + (size_t)(bn + arow) * K + acol * 8;

    float acc[4][8][4];
#pragma unroll
    for (int mt = 0; mt < 4; mt++)
#pragma unroll
        for (int nt = 0; nt < 8; nt++)
#pragma unroll
            for (int i = 0; i < 4; i++) acc[mt][nt][i] = 0.f;

    const int nst = K / 32;

#define G_ISSUE(s)                                                               \
    {                                                                            \
        const int bf_ = (s) & 3;                                                 \
        const __half* ap_ = Ap + (size_t)(s) * 32;                               \
        const __half* wp_ = Wp + (size_t)(s) * 32;                               \
        uint32_t da_ = asb + (uint32_t)(bf_ * SAB + arow * APB + acol * 16);     \
        uint32_t db_ = bsb + (uint32_t)(bf_ * SBB + arow * APB + acol * 16);     \
        _Pragma("unroll")                                                        \
        for (int i_ = 0; i_ < 4; i_++)                                           \
            cpa16(da_ + (uint32_t)(i_ * 64 * APB), ap_ + (size_t)i_ * 64 * K);   \
        _Pragma("unroll")                                                        \
        for (int i_ = 0; i_ < 2; i_++)                                           \
            cpa16(db_ + (uint32_t)(i_ * 64 * APB), wp_ + (size_t)i_ * 64 * K);   \
        cpa_commit();                                                            \
    }

    G_ISSUE(0);
    G_ISSUE(1);

    for (int s = 0; s < nst; s++) {
        const int buf = s & 3;
        if (s + 2 < nst) G_ISSUE(s + 2);
        const int rem = nst - 1 - s;
        if (rem >= 2) cpa_wait<2>();
        else if (rem == 1) cpa_wait<1>();
        else cpa_wait<0>();
        __syncthreads();

        const uint32_t abase = asb + (uint32_t)(buf * SAB + wm * 64 * APB);
        const uint32_t bbase = bsb + (uint32_t)(buf * SBB + wn * 64 * APB);
#pragma unroll
        for (int ks = 0; ks < 2; ks++) {
            uint32_t af[4][4], bf[8][2];
#pragma unroll
            for (int mt = 0; mt < 4; mt++)
                ldsm4(af[mt][0], af[mt][1], af[mt][2], af[mt][3],
                      abase + (uint32_t)((mt * 16 + lrow) * APB + ks * 32) + hi16);
#pragma unroll
            for (int p = 0; p < 4; p++) {
                uint32_t r0, r1, r2, r3;
                ldsm4(r0, r1, r2, r3,
                      bbase + (uint32_t)((p * 16 + lrow) * APB + ks * 32) + hi16);
                bf[2 * p][0] = r0; bf[2 * p + 1][0] = r1;
                bf[2 * p][1] = r2; bf[2 * p + 1][1] = r3;
            }
#pragma unroll
            for (int mt = 0; mt < 4; mt++)
#pragma unroll
                for (int nt = 0; nt < 8; nt++) mma16(acc[mt][nt], af[mt], bf[nt]);
        }
    }

    const int g = lane >> 2, t = lane & 3;
#pragma unroll
    for (int mt = 0; mt < 4; mt++)
#pragma unroll
        for (int nt = 0; nt < 8; nt++) {
            int row = bm + wm * 64 + mt * 16 + g;
            int col = bn + wn * 64 + nt * 8 + 2 * t;
            *(float2*)(C + (size_t)row * ldc + col) =
                make_float2(acc[mt][nt][0], acc[mt][nt][1]);
            *(float2*)(C + (size_t)(row + 8) * ldc + col) =
                make_float2(acc[mt][nt][2], acc[mt][nt][3]);
        }
#undef G_ISSUE
}

// ---------------------------------------------------------------------------
// Copy KV caches into fp16 scratch
// ---------------------------------------------------------------------------
__global__ void copy_caches(const float4* __restrict__ ck, const float4* __restrict__ cv)
{
    const int n = B_ * KVH_ * KV_ * D_ / 4;
    __half2* dk = (__half2*)g_kh;
    __half2* dv = (__half2*)g_vh;
    for (int i = blockIdx.x * blockDim.x + threadIdx.x; i < n;
         i += gridDim.x * blockDim.x) {
        float4 a = ck[i];
        dk[2 * i]     = __floats2half2_rn(a.x, a.y);
        dk[2 * i + 1] = __floats2half2_rn(a.z, a.w);
        float4 b = cv[i];
        dv[2 * i]     = __floats2half2_rn(b.x, b.y);
        dv[2 * i + 1] = __floats2half2_rn(b.z, b.w);
    }
}

// ---------------------------------------------------------------------------
// RoPE + scatter; Q pre-scaled by 1/sqrt(D); fp16 outputs
// ---------------------------------------------------------------------------
__global__ void rope_scatter(const float* __restrict__ cosp,
                             const float* __restrict__ sinp,
                             const int*   __restrict__ sink)
{
    int idx = blockIdx.x * blockDim.x + threadIdx.x;
    const int total = B_ * Q_ * (H_ + 2 * KVH_) * D_;
    if (idx >= total) return;
    int d = idx & (D_ - 1);
    int t = idx >> 7;
    int head = t % (H_ + 2 * KVH_); t /= (H_ + 2 * KVH_);
    int q = t % Q_;
    int b = t / Q_;
    const float* row = g_qkv + (size_t)(b * Q_ + q) * QKVN_;

    if (head < H_ + KVH_) {
        float c = cosp[(size_t)(b * Q_ + q) * D_ + d];
        float s = sinp[(size_t)(b * Q_ + q) * D_ + d];
        int off = (head < H_) ? head * D_ : (H_ * D_ + (head - H_) * D_);
        float x  = row[off + d];
        float xp = (d < D_ / 2) ? row[off + d + D_ / 2] : row[off + d - D_ / 2];
        float r  = (d < D_ / 2) ? (x * c - xp * s) : (x * c + xp * s);
        if (head < H_) {
            g_qh[((size_t)(b * H_ + head) * Q_ + q) * D_ + d] =
                __float2half_rn(r * 0.08838834764831845f);
        } else {
            int kvh = head - H_;
            int sid = sink[q];
            g_kh[((size_t)(b * KVH_ + kvh) * KV_ + sid) * D_ + d] = __float2half_rn(r);
        }
    } else {
        int kvh = head - H_ - KVH_;
        int sid = sink[q];
        g_vh[((size_t)(b * KVH_ + kvh) * KV_ + sid) * D_ + d] =
            __float2half_rn(row[(H_ + KVH_) * D_ + kvh * D_ + d]);
    }
}

// ---------------------------------------------------------------------------
// Flash attention, fp16 mma, register-resident P.
// Block = 128 q-rows x one (b,h). 256 threads / 8 warps; warp w owns q-rows
// [16w,16w+16) in BOTH phases: the S-GEMM C-fragment layout is identical to
// the PV-GEMM A-fragment layout, so P never touches smem. Per-warp softmax
// stats in registers -> NO cross-warp communication, ONE barrier per tile.
// K/V/mask tiles cp.async'd through a 3-deep ring (mask pre-cvt to fp16).
// ---------------------------------------------------------------------------
#define KPB 272                 // K/V smem row pitch bytes
#define KTB (64 * KPB)          // 17408 per K or V tile
#define MPB 144                 // mask smem row pitch bytes (72 halfs)
#define MTB (128 * MPB)         // 18432 per mask tile
#define STG_ (2 * KTB + MTB)    // 53248 per ring stage
#define ATTN_SMEM (3 * STG_)    // 159744
__global__ __launch_bounds__(256, 1) void attn_h(const __half* __restrict__ mh)
{
    extern __shared__ char sm[];
    const uint32_t smb = smem_u32(sm);

    const int tid = threadIdx.x, lane = tid & 31, w = tid >> 5;
    const int b = blockIdx.z, h = blockIdx.y, q0 = blockIdx.x * 128;
    const int kvh = h / NREP_;
    const int g = lane >> 2, t = lane & 3;
    const int lrow = lane & 15;
    const uint32_t hi16 = (uint32_t)((lane >> 4) << 4);
    const int r0 = w * 16 + g;

    const __half* Kb = g_kh + (size_t)(b * KVH_ + kvh) * KV_ * D_;
    const __half* Vb = g_vh + (size_t)(b * KVH_ + kvh) * KV_ * D_;
    const __half* Mb = mh + ((size_t)b * Q_ + q0) * KV_;

    const int crow = tid >> 4, ccol = tid & 15;    // K/V cp.async mapping
    const int mrow = tid >> 1, mc = (tid & 1) * 4; // mask cp.async mapping

#define KV_ISSUE(it_)                                                            \
    {                                                                            \
        const uint32_t base_ = smb + (uint32_t)(((it_) % 3) * STG_);             \
        const __half* Kg_ = Kb + (size_t)((it_) * 64) * D_;                      \
        const __half* Vg_ = Vb + (size_t)((it_) * 64) * D_;                      \
        _Pragma("unroll")                                                        \
        for (int i_ = 0; i_ < 4; i_++) {                                         \
            cpa16(base_ + (uint32_t)((crow + 16 * i_) * KPB + ccol * 16),        \
                  Kg_ + (size_t)(crow + 16 * i_) * D_ + ccol * 8);               \
            cpa16(base_ + (uint32_t)(KTB + (crow + 16 * i_) * KPB + ccol * 16),  \
                  Vg_ + (size_t)(crow + 16 * i_) * D_ + ccol * 8);               \
        }                                                                        \
        _Pragma("unroll")                                                        \
        for (int i_ = 0; i_ < 4; i_++)                                           \
            cpa16(base_ + (uint32_t)(2 * KTB + mrow * MPB + (mc + i_) * 16),     \
                  Mb + (size_t)mrow * KV_ + (it_) * 64 + (mc + i_) * 8);         \
        cpa_commit();                                                            \
    }

    KV_ISSUE(0);
    KV_ISSUE(1);

    // preload Q fragments (fp16): 8 k16-steps
    const __half* Qg = g_qh + ((size_t)(b * H_ + h) * Q_ + q0 + w * 16) * D_;
    uint32_t qf[8][4];
#pragma unroll
    for (int ks = 0; ks < 8; ks++) {
        const __half* qp = Qg + (size_t)g * D_ + ks * 16 + 2 * t;
        qf[ks][0] = *(const uint32_t*)qp;
        qf[ks][1] = *(const uint32_t*)(qp + (size_t)8 * D_);
        qf[ks][2] = *(const uint32_t*)(qp + 8);
        qf[ks][3] = *(const uint32_t*)(qp + (size_t)8 * D_ + 8);
    }

    float accO[16][4];
#pragma unroll
    for (int nt = 0; nt < 16; nt++)
#pragma unroll
        for (int i = 0; i < 4; i++) accO[nt][i] = 0.f;

    float m0 = -1e30f, m1 = -1e30f, l0 = 0.f, l1 = 0.f;

    const int NT = KV_ / 64;
    for (int it = 0; it < NT; it++) {
        if (it + 1 < NT) cpa_wait<1>(); else cpa_wait<0>();
        __syncthreads();                 // tile visible + everyone done with it-1
        if (it + 2 < NT) KV_ISSUE(it + 2);

        const uint32_t kbase = smb + (uint32_t)((it % 3) * STG_);
        const uint32_t vbase = kbase + (uint32_t)KTB;
        const __half* sMh = (const __half*)(sm + (size_t)(it % 3) * STG_ + 2 * KTB);

        // ---- S = Q @ K^T + mask (mask from smem into accumulator init) ----
        float sacc[8][4];
#pragma unroll
        for (int nt = 0; nt < 8; nt++) {
            float2 f0 = __half22float2(
                *(const __half2*)(sMh + (size_t)r0 * 72 + nt * 8 + 2 * t));
            float2 f1 = __half22float2(
                *(const __half2*)(sMh + (size_t)(r0 + 8) * 72 + nt * 8 + 2 * t));
            sacc[nt][0] = f0.x; sacc[nt][1] = f0.y;
            sacc[nt][2] = f1.x; sacc[nt][3] = f1.y;
        }
#pragma unroll
        for (int ks = 0; ks < 8; ks++) {
            uint32_t bf[8][2];
#pragma unroll
            for (int p = 0; p < 4; p++) {
                uint32_t r0w, r1w, r2w, r3w;
                ldsm4(r0w, r1w, r2w, r3w,
                      kbase + (uint32_t)((p * 16 + lrow) * KPB + ks * 32) + hi16);
                bf[2 * p][0] = r0w; bf[2 * p + 1][0] = r1w;
                bf[2 * p][1] = r2w; bf[2 * p + 1][1] = r3w;
            }
#pragma unroll
            for (int nt = 0; nt < 8; nt++) mma16(sacc[nt], qf[ks], bf[nt]);
        }

        // ---- register softmax (rows r0, r0+8; quad owns a row) ----
        float mx0 = -1e30f, mx1 = -1e30f;
#pragma unroll
        for (int nt = 0; nt < 8; nt++) {
            mx0 = fmaxf(mx0, fmaxf(sacc[nt][0], sacc[nt][1]));
            mx1 = fmaxf(mx1, fmaxf(sacc[nt][2], sacc[nt][3]));
        }
        mx0 = fmaxf(mx0, __shfl_xor_sync(0xffffffffu, mx0, 1));
        mx0 = fmaxf(mx0, __shfl_xor_sync(0xffffffffu, mx0, 2));
        mx1 = fmaxf(mx1, __shfl_xor_sync(0xffffffffu, mx1, 1));
        mx1 = fmaxf(mx1, __shfl_xor_sync(0xffffffffu, mx1, 2));
        float mn0 = fmaxf(m0, mx0), mn1 = fmaxf(m1, mx1);
        float ss0 = 0.f, ss1 = 0.f;
#pragma unroll
        for (int nt = 0; nt < 8; nt++) {
            sacc[nt][0] = __expf(sacc[nt][0] - mn0);
            sacc[nt][1] = __expf(sacc[nt][1] - mn0);
            sacc[nt][2] = __expf(sacc[nt][2] - mn1);
            sacc[nt][3] = __expf(sacc[nt][3] - mn1);
            ss0 += sacc[nt][0] + sacc[nt][1];
            ss1 += sacc[nt][2] + sacc[nt][3];
        }
        ss0 += __shfl_xor_sync(0xffffffffu, ss0, 1);
        ss0 += __shfl_xor_sync(0xffffffffu, ss0, 2);
        ss1 += __shfl_xor_sync(0xffffffffu, ss1, 1);
        ss1 += __shfl_xor_sync(0xffffffffu, ss1, 2);
        float c0 = __expf(m0 - mn0), c1 = __expf(m1 - mn1);
        l0 = l0 * c0 + ss0; l1 = l1 * c1 + ss1;
        m0 = mn0; m1 = mn1;

        // ---- scale accO; pack P to fp16 A-fragments (identity re-layout) ----
#pragma unroll
        for (int nt = 0; nt < 16; nt++) {
            accO[nt][0] *= c0; accO[nt][1] *= c0;
            accO[nt][2] *= c1; accO[nt][3] *= c1;
        }
        uint32_t ph[4][4];
#pragma unroll
        for (int ks = 0; ks < 4; ks++) {
            ph[ks][0] = pack_h2(sacc[2 * ks][0], sacc[2 * ks][1]);
            ph[ks][1] = pack_h2(sacc[2 * ks][2], sacc[2 * ks][3]);
            ph[ks][2] = pack_h2(sacc[2 * ks + 1][0], sacc[2 * ks + 1][1]);
            ph[ks][3] = pack_h2(sacc[2 * ks + 1][2], sacc[2 * ks + 1][3]);
        }

        // ---- O += P @ V (warp: its 16 q-rows x all 128 d-cols) ----
#pragma unroll
        for (int ks = 0; ks < 4; ks++) {
            uint32_t bf[16][2];
#pragma unroll
            for (int p = 0; p < 8; p++) {
                uint32_t r0w, r1w, r2w, r3w;
                ldsm4t(r0w, r1w, r2w, r3w,
                       vbase + (uint32_t)((ks * 16 + lrow) * KPB + p * 32) + hi16);
                bf[2 * p][0] = r0w; bf[2 * p][1] = r1w;
                bf[2 * p + 1][0] = r2w; bf[2 * p + 1][1] = r3w;
            }
#pragma unroll
            for (int nt = 0; nt < 16; nt++) mma16(accO[nt], ph[ks], bf[nt]);
        }
    }

    // ---- write O (fp16, consumed by Wo GEMM); stats are in registers ----
    float i0 = 1.f / l0, i1 = 1.f / l1;
    __half* op  = g_attnh + (size_t)(b * Q_ + q0 + r0) * (H_ * D_) + h * D_;
    __half* op8 = op + (size_t)8 * (H_ * D_);
#pragma unroll
    for (int nt = 0; nt < 16; nt++) {
        *(__half2*)(op  + nt * 8 + 2 * t) =
            __floats2half2_rn(accO[nt][0] * i0, accO[nt][1] * i0);
        *(__half2*)(op8 + nt * 8 + 2 * t) =
            __floats2half2_rn(accO[nt][2] * i1, accO[nt][3] * i1);
    }
#undef KV_ISSUE
}

// ---------------------------------------------------------------------------
extern "C" void kernel_launch(void* const* d_in, const int* in_sizes, int n_in,
                              void* d_out, int out_size)
{
    const float* hidden = (const float*)d_in[0];
    const float* cosp   = (const float*)d_in[1];
    const float* sinp   = (const float*)d_in[2];
    const float* mask   = (const float*)d_in[3];
    const float* ck     = (const float*)d_in[4];
    const float* cv     = (const float*)d_in[5];
    const int*   sink   = (const int*)d_in[6];
    const float* Wq     = (const float*)d_in[7];
    const float* Wk     = (const float*)d_in[8];
    const float* Wv     = (const float*)d_in[9];
    const float* Wo     = (const float*)d_in[10];
    float* out = (float*)d_out;

    float  *qkv_p = nullptr;
    __half *hidh_p = nullptr, *wh_p = nullptr, *woh_p = nullptr;
    __half *attnh_p = nullptr, *mh_p = nullptr;
    cudaGetSymbolAddress((void**)&qkv_p, g_qkv);
    cudaGetSymbolAddress((void**)&hidh_p, g_hidh);
    cudaGetSymbolAddress((void**)&wh_p, g_wh);
    cudaGetSymbolAddress((void**)&woh_p, g_woh);
    cudaGetSymbolAddress((void**)&attnh_p, g_attnh);
    cudaGetSymbolAddress((void**)&mh_p, g_mh);

    // fp32 -> fp16 conversions (bandwidth-bound)
    {
        int n4h = M_ * HID_ / 4;
        cvt_half_k<<<(n4h + 255) / 256, 256>>>((const float4*)hidden, (__half2*)hidh_p, n4h);
        int n4q = H_ * D_ * HID_ / 4;
        cvt_half_k<<<(n4q + 255) / 256, 256>>>((const float4*)Wq, (__half2*)wh_p, n4q);
        int n4k = KVH_ * D_ * HID_ / 4;
        cvt_half_k<<<(n4k + 255) / 256, 256>>>((const float4*)Wk,
            (__half2*)(wh_p + (size_t)H_ * D_ * HID_), n4k);
        cvt_half_k<<<(n4k + 255) / 256, 256>>>((const float4*)Wv,
            (__half2*)(wh_p + (size_t)(H_ + KVH_) * D_ * HID_), n4k);
        int n4o = HID_ * H_ * D_ / 4;
        cvt_half_k<<<(n4o + 255) / 256, 256>>>((const float4*)Wo, (__half2*)woh_p, n4o);
        int n4m = B_ * Q_ * KV_ / 4;
        cvt_mask_k<<<(n4m + 255) / 256, 256>>>((const float4*)mask, (__half2*)mh_p, n4m);
    }

    const int smem_gemm = 4 * (SAB + SBB);   // 122880 B
    cudaFuncSetAttribute(gemm_h, cudaFuncAttributeMaxDynamicSharedMemorySize, smem_gemm);

    // Fused QKV projection
    gemm_h<<<dim3(QKVN_ / 128, M_ / 256), 256, smem_gemm>>>(
        hidh_p, wh_p, qkv_p, HID_, QKVN_);

    // KV cache copy (fp16) + RoPE/scatter (fp16)
    copy_caches<<<2048, 256>>>((const float4*)ck, (const float4*)cv);
    {
        int total = B_ * Q_ * (H_ + 2 * KVH_) * D_;
        rope_scatter<<<(total + 255) / 256, 256>>>(cosp, sinp, sink);
    }

    // Attention
    cudaFuncSetAttribute(attn_h, cudaFuncAttributeMaxDynamicSharedMemorySize, ATTN_SMEM);
    attn_h<<<dim3(Q_ / 128, H_, B_), 256, ATTN_SMEM>>>(mh_p);

    // Output projection -> d_out
    gemm_h<<<dim3(HID_ / 128, M_ / 256), 256, smem_gemm>>>(
        attnh_p, woh_p, out, H_ * D_, HID_);
}

// round 17
// speedup vs baseline: 16.0622x; 1.0526x over previous
#include <cuda_runtime.h>
#include <cuda_fp16.h>
#include <math.h>
#include <stdint.h>

// Problem constants
#define B_    2
#define Q_    1024
#define H_    32
#define KVH_  8
#define D_    128
#define KV_   4096
#define HID_  4096
#define NREP_ (H_ / KVH_)
#define M_    (B_ * Q_)              // 2048
#define QKVN_ ((H_ + 2 * KVH_) * D_) // 6144

#define LOG2E 1.4426950408889634f

// Static device scratch (allocation-free rule)
__device__ float  g_qkv [(size_t)M_ * QKVN_];            // fp32 GEMM out
__device__ __half g_hidh[(size_t)M_ * HID_];             // fp16 hidden
__device__ __half g_wh  [(size_t)QKVN_ * HID_];          // fp16 [Wq|Wk|Wv]
__device__ __half g_woh [(size_t)HID_ * (H_ * D_)];      // fp16 Wo
__device__ __half g_qh  [(size_t)B_ * H_  * Q_  * D_];   // fp16 Q (pre-scaled incl log2e)
__device__ __half g_kh  [(size_t)B_ * KVH_ * KV_ * D_];  // fp16 K cache
__device__ __half g_vh  [(size_t)B_ * KVH_ * KV_ * D_];  // fp16 V cache
__device__ __half g_attnh[(size_t)M_ * H_ * D_];         // fp16 attn out
__device__ __half g_mh  [(size_t)B_ * Q_ * KV_];         // fp16 mask (x log2e, clamped)

// ---------------------------------------------------------------------------
// helpers
// ---------------------------------------------------------------------------
__device__ __forceinline__ void mma16(float c[4], const uint32_t a[4], const uint32_t b[2]) {
    asm volatile(
        "mma.sync.aligned.m16n8k16.row.col.f32.f16.f16.f32 "
        "{%0,%1,%2,%3}, {%4,%5,%6,%7}, {%8,%9}, {%0,%1,%2,%3};\n"
        : "+f"(c[0]), "+f"(c[1]), "+f"(c[2]), "+f"(c[3])
        : "r"(a[0]), "r"(a[1]), "r"(a[2]), "r"(a[3]), "r"(b[0]), "r"(b[1]));
}

// pack two fp32 into one fp16x2 register (rn)
__device__ __forceinline__ uint32_t pack_h2(float lo, float hi) {
    uint32_t r;
    asm("cvt.rn.f16x2.f32 %0, %1, %2;" : "=r"(r) : "f"(hi), "f"(lo));
    return r;
}

__device__ __forceinline__ uint32_t smem_u32(const void* p) {
    return (uint32_t)__cvta_generic_to_shared(p);
}

__device__ __forceinline__ void ldsm4(uint32_t& r0, uint32_t& r1, uint32_t& r2,
                                      uint32_t& r3, uint32_t addr) {
    asm volatile("ldmatrix.sync.aligned.m8n8.x4.shared.b16 {%0,%1,%2,%3}, [%4];"
                 : "=r"(r0), "=r"(r1), "=r"(r2), "=r"(r3) : "r"(addr));
}
__device__ __forceinline__ void ldsm4t(uint32_t& r0, uint32_t& r1, uint32_t& r2,
                                       uint32_t& r3, uint32_t addr) {
    asm volatile("ldmatrix.sync.aligned.m8n8.x4.trans.shared.b16 {%0,%1,%2,%3}, [%4];"
                 : "=r"(r0), "=r"(r1), "=r"(r2), "=r"(r3) : "r"(addr));
}

__device__ __forceinline__ void cpa16(uint32_t dst, const void* src) {
    asm volatile("cp.async.cg.shared.global [%0], [%1], 16;" :: "r"(dst), "l"(src));
}
__device__ __forceinline__ void cpa_commit() {
    asm volatile("cp.async.commit_group;" ::: "memory");
}
template <int N> __device__ __forceinline__ void cpa_wait() {
    asm volatile("cp.async.wait_group %0;" :: "n"(N) : "memory");
}

// ---------------------------------------------------------------------------
// fp32 -> fp16 conversions (bandwidth-bound)
// ---------------------------------------------------------------------------
__global__ void cvt_half_k(const float4* __restrict__ src, __half2* __restrict__ dst,
                           int n4)
{
    int i = blockIdx.x * blockDim.x + threadIdx.x;
    if (i >= n4) return;
    float4 v = src[i];
    dst[2 * i]     = __floats2half2_rn(v.x, v.y);
    dst[2 * i + 1] = __floats2half2_rn(v.z, v.w);
}

// mask: scale by log2e (for exp2 softmax), clamp to finite fp16 range
__global__ void cvt_mask_k(const float4* __restrict__ src, __half2* __restrict__ dst,
                           int n4)
{
    int i = blockIdx.x * blockDim.x + threadIdx.x;
    if (i >= n4) return;
    float4 v = src[i];
    v.x = fmaxf(v.x * LOG2E, -60000.f); v.y = fmaxf(v.y * LOG2E, -60000.f);
    v.z = fmaxf(v.z * LOG2E, -60000.f); v.w = fmaxf(v.w * LOG2E, -60000.f);
    dst[2 * i]     = __floats2half2_rn(v.x, v.y);
    dst[2 * i + 1] = __floats2half2_rn(v.z, v.w);
}

// ---------------------------------------------------------------------------
// fp16 GEMM, cp.async pipelined (unchanged from R16 passing version)
// ---------------------------------------------------------------------------
#define APB 80
#define SAB (256 * APB)
#define SBB (128 * APB)
__global__ __launch_bounds__(256) void gemm_h(
    const __half* __restrict__ A, const __half* __restrict__ W,
    float* __restrict__ C, int K, int ldc)
{
    extern __shared__ char sm[];
    const uint32_t asb = smem_u32(sm);
    const uint32_t bsb = asb + 4 * SAB;

    const int tid = threadIdx.x, lane = tid & 31, wid = tid >> 5;
    const int wm = wid >> 1, wn = wid & 1;
    const int bm = blockIdx.y * 256, bn = blockIdx.x * 128;
    const int lrow = lane & 15;
    const uint32_t hi16 = (uint32_t)((lane >> 4) << 4);

    const int arow = tid >> 2, acol = tid & 3;
    const __half* Ap = A + (size_t)(bm + arow) * K + acol * 8;
    const __half* Wp = W + (size_t)(bn + arow) * K + acol * 8;

    float acc[4][8][4];
#pragma unroll
    for (int mt = 0; mt < 4; mt++)
#pragma unroll
        for (int nt = 0; nt < 8; nt++)
#pragma unroll
            for (int i = 0; i < 4; i++) acc[mt][nt][i] = 0.f;

    const int nst = K / 32;

#define G_ISSUE(s)                                                               \
    {                                                                            \
        const int bf_ = (s) & 3;                                                 \
        const __half* ap_ = Ap + (size_t)(s) * 32;                               \
        const __half* wp_ = Wp + (size_t)(s) * 32;                               \
        uint32_t da_ = asb + (uint32_t)(bf_ * SAB + arow * APB + acol * 16);     \
        uint32_t db_ = bsb + (uint32_t)(bf_ * SBB + arow * APB + acol * 16);     \
        _Pragma("unroll")                                                        \
        for (int i_ = 0; i_ < 4; i_++)                                           \
            cpa16(da_ + (uint32_t)(i_ * 64 * APB), ap_ + (size_t)i_ * 64 * K);   \
        _Pragma("unroll")                                                        \
        for (int i_ = 0; i_ < 2; i_++)                                           \
            cpa16(db_ + (uint32_t)(i_ * 64 * APB), wp_ + (size_t)i_ * 64 * K);   \
        cpa_commit();                                                            \
    }

    G_ISSUE(0);
    G_ISSUE(1);

    for (int s = 0; s < nst; s++) {
        const int buf = s & 3;
        if (s + 2 < nst) G_ISSUE(s + 2);
        const int rem = nst - 1 - s;
        if (rem >= 2) cpa_wait<2>();
        else if (rem == 1) cpa_wait<1>();
        else cpa_wait<0>();
        __syncthreads();

        const uint32_t abase = asb + (uint32_t)(buf * SAB + wm * 64 * APB);
        const uint32_t bbase = bsb + (uint32_t)(buf * SBB + wn * 64 * APB);
#pragma unroll
        for (int ks = 0; ks < 2; ks++) {
            uint32_t af[4][4], bf[8][2];
#pragma unroll
            for (int mt = 0; mt < 4; mt++)
                ldsm4(af[mt][0], af[mt][1], af[mt][2], af[mt][3],
                      abase + (uint32_t)((mt * 16 + lrow) * APB + ks * 32) + hi16);
#pragma unroll
            for (int p = 0; p < 4; p++) {
                uint32_t r0, r1, r2, r3;
                ldsm4(r0, r1, r2, r3,
                      bbase + (uint32_t)((p * 16 + lrow) * APB + ks * 32) + hi16);
                bf[2 * p][0] = r0; bf[2 * p + 1][0] = r1;
                bf[2 * p][1] = r2; bf[2 * p + 1][1] = r3;
            }
#pragma unroll
            for (int mt = 0; mt < 4; mt++)
#pragma unroll
                for (int nt = 0; nt < 8; nt++) mma16(acc[mt][nt], af[mt], bf[nt]);
        }
    }

    const int g = lane >> 2, t = lane & 3;
#pragma unroll
    for (int mt = 0; mt < 4; mt++)
#pragma unroll
        for (int nt = 0; nt < 8; nt++) {
            int row = bm + wm * 64 + mt * 16 + g;
            int col = bn + wn * 64 + nt * 8 + 2 * t;
            *(float2*)(C + (size_t)row * ldc + col) =
                make_float2(acc[mt][nt][0], acc[mt][nt][1]);
            *(float2*)(C + (size_t)(row + 8) * ldc + col) =
                make_float2(acc[mt][nt][2], acc[mt][nt][3]);
        }
#undef G_ISSUE
}

// ---------------------------------------------------------------------------
// Copy KV caches into fp16 scratch
// ---------------------------------------------------------------------------
__global__ void copy_caches(const float4* __restrict__ ck, const float4* __restrict__ cv)
{
    const int n = B_ * KVH_ * KV_ * D_ / 4;
    __half2* dk = (__half2*)g_kh;
    __half2* dv = (__half2*)g_vh;
    for (int i = blockIdx.x * blockDim.x + threadIdx.x; i < n;
         i += gridDim.x * blockDim.x) {
        float4 a = ck[i];
        dk[2 * i]     = __floats2half2_rn(a.x, a.y);
        dk[2 * i + 1] = __floats2half2_rn(a.z, a.w);
        float4 b = cv[i];
        dv[2 * i]     = __floats2half2_rn(b.x, b.y);
        dv[2 * i + 1] = __floats2half2_rn(b.z, b.w);
    }
}

// ---------------------------------------------------------------------------
// RoPE + scatter; Q pre-scaled by log2e/sqrt(D); fp16 outputs
// ---------------------------------------------------------------------------
__global__ void rope_scatter(const float* __restrict__ cosp,
                             const float* __restrict__ sinp,
                             const int*   __restrict__ sink)
{
    int idx = blockIdx.x * blockDim.x + threadIdx.x;
    const int total = B_ * Q_ * (H_ + 2 * KVH_) * D_;
    if (idx >= total) return;
    int d = idx & (D_ - 1);
    int t = idx >> 7;
    int head = t % (H_ + 2 * KVH_); t /= (H_ + 2 * KVH_);
    int q = t % Q_;
    int b = t / Q_;
    const float* row = g_qkv + (size_t)(b * Q_ + q) * QKVN_;

    if (head < H_ + KVH_) {
        float c = cosp[(size_t)(b * Q_ + q) * D_ + d];
        float s = sinp[(size_t)(b * Q_ + q) * D_ + d];
        int off = (head < H_) ? head * D_ : (H_ * D_ + (head - H_) * D_);
        float x  = row[off + d];
        float xp = (d < D_ / 2) ? row[off + d + D_ / 2] : row[off + d - D_ / 2];
        float r  = (d < D_ / 2) ? (x * c - xp * s) : (x * c + xp * s);
        if (head < H_) {
            g_qh[((size_t)(b * H_ + head) * Q_ + q) * D_ + d] =
                __float2half_rn(r * (0.08838834764831845f * LOG2E));
        } else {
            int kvh = head - H_;
            int sid = sink[q];
            g_kh[((size_t)(b * KVH_ + kvh) * KV_ + sid) * D_ + d] = __float2half_rn(r);
        }
    } else {
        int kvh = head - H_ - KVH_;
        int sid = sink[q];
        g_vh[((size_t)(b * KVH_ + kvh) * KV_ + sid) * D_ + d] =
            __float2half_rn(row[(H_ + KVH_) * D_ + kvh * D_ + d]);
    }
}

// ---------------------------------------------------------------------------
// Flash attention, fp16 mma, register-resident P, 2 CTAs/SM.
// Block = 64 q-rows x one (b,h). 128 threads / 4 warps; warp w owns q-rows
// [16w,16w+16) in both phases (S C-frag == PV A-frag, P stays in registers).
// Softmax via exp2 (log2e folded into Q and mask). 2-stage cp.async ring,
// distance-1 prefetch, ONE barrier per tile. 88KB smem/CTA -> 2 CTAs/SM
// (by regs and smem) so softmax of one CTA overlaps MMA of the other.
// ---------------------------------------------------------------------------
#define KPB 272                 // K/V smem row pitch bytes
#define KTB (64 * KPB)          // 17408 per K or V tile
#define MPB 144                 // mask smem row pitch bytes (72 halfs)
#define MTB (64 * MPB)          // 9216 per mask tile (64 rows)
#define STG_ (2 * KTB + MTB)    // 44032 per ring stage
#define ATTN_SMEM (2 * STG_)    // 88064
__global__ __launch_bounds__(128, 2) void attn_h(const __half* __restrict__ mh)
{
    extern __shared__ char sm[];
    const uint32_t smb = smem_u32(sm);

    const int tid = threadIdx.x, lane = tid & 31, w = tid >> 5;
    const int b = blockIdx.z, h = blockIdx.y, q0 = blockIdx.x * 64;
    const int kvh = h / NREP_;
    const int g = lane >> 2, t = lane & 3;
    const int lrow = lane & 15;
    const uint32_t hi16 = (uint32_t)((lane >> 4) << 4);
    const int r0 = w * 16 + g;

    const __half* Kb = g_kh + (size_t)(b * KVH_ + kvh) * KV_ * D_;
    const __half* Vb = g_vh + (size_t)(b * KVH_ + kvh) * KV_ * D_;
    const __half* Mb = mh + ((size_t)b * Q_ + q0) * KV_;

    const int crow = tid >> 4, ccol = tid & 15;    // K/V cp.async: 8 rows/pass
    const int mrow = tid >> 1, mc = (tid & 1) * 4; // mask: 2 thr/row, 4 chunks

#define KV_ISSUE(it_)                                                            \
    {                                                                            \
        const uint32_t base_ = smb + (uint32_t)(((it_) & 1) * STG_);             \
        const __half* Kg_ = Kb + (size_t)((it_) * 64) * D_;                      \
        const __half* Vg_ = Vb + (size_t)((it_) * 64) * D_;                      \
        _Pragma("unroll")                                                        \
        for (int i_ = 0; i_ < 8; i_++) {                                         \
            cpa16(base_ + (uint32_t)((crow + 8 * i_) * KPB + ccol * 16),         \
                  Kg_ + (size_t)(crow + 8 * i_) * D_ + ccol * 8);                \
            cpa16(base_ + (uint32_t)(KTB + (crow + 8 * i_) * KPB + ccol * 16),   \
                  Vg_ + (size_t)(crow + 8 * i_) * D_ + ccol * 8);                \
        }                                                                        \
        _Pragma("unroll")                                                        \
        for (int i_ = 0; i_ < 4; i_++)                                           \
            cpa16(base_ + (uint32_t)(2 * KTB + mrow * MPB + (mc + i_) * 16),     \
                  Mb + (size_t)mrow * KV_ + (it_) * 64 + (mc + i_) * 8);         \
        cpa_commit();                                                            \
    }

    KV_ISSUE(0);

    // preload Q fragments (fp16): 8 k16-steps
    const __half* Qg = g_qh + ((size_t)(b * H_ + h) * Q_ + q0 + w * 16) * D_;
    uint32_t qf[8][4];
#pragma unroll
    for (int ks = 0; ks < 8; ks++) {
        const __half* qp = Qg + (size_t)g * D_ + ks * 16 + 2 * t;
        qf[ks][0] = *(const uint32_t*)qp;
        qf[ks][1] = *(const uint32_t*)(qp + (size_t)8 * D_);
        qf[ks][2] = *(const uint32_t*)(qp + 8);
        qf[ks][3] = *(const uint32_t*)(qp + (size_t)8 * D_ + 8);
    }

    float accO[16][4];
#pragma unroll
    for (int nt = 0; nt < 16; nt++)
#pragma unroll
        for (int i = 0; i < 4; i++) accO[nt][i] = 0.f;

    float m0 = -1e30f, m1 = -1e30f, l0 = 0.f, l1 = 0.f;

    const int NT = KV_ / 64;
    for (int it = 0; it < NT; it++) {
        cpa_wait<0>();                  // tile it arrived (sole outstanding group)
        __syncthreads();                // visible to all; everyone done with it-1
        if (it + 1 < NT) KV_ISSUE(it + 1);   // overlaps with compute below

        const uint32_t kbase = smb + (uint32_t)((it & 1) * STG_);
        const uint32_t vbase = kbase + (uint32_t)KTB;
        const __half* sMh = (const __half*)(sm + (size_t)(it & 1) * STG_ + 2 * KTB);

        // ---- S = Q @ K^T + mask (mask from smem into accumulator init) ----
        float sacc[8][4];
#pragma unroll
        for (int nt = 0; nt < 8; nt++) {
            float2 f0 = __half22float2(
                *(const __half2*)(sMh + (size_t)r0 * 72 + nt * 8 + 2 * t));
            float2 f1 = __half22float2(
                *(const __half2*)(sMh + (size_t)(r0 + 8) * 72 + nt * 8 + 2 * t));
            sacc[nt][0] = f0.x; sacc[nt][1] = f0.y;
            sacc[nt][2] = f1.x; sacc[nt][3] = f1.y;
        }
#pragma unroll
        for (int ks = 0; ks < 8; ks++) {
            uint32_t bf[8][2];
#pragma unroll
            for (int p = 0; p < 4; p++) {
                uint32_t r0w, r1w, r2w, r3w;
                ldsm4(r0w, r1w, r2w, r3w,
                      kbase + (uint32_t)((p * 16 + lrow) * KPB + ks * 32) + hi16);
                bf[2 * p][0] = r0w; bf[2 * p + 1][0] = r1w;
                bf[2 * p][1] = r2w; bf[2 * p + 1][1] = r3w;
            }
#pragma unroll
            for (int nt = 0; nt < 8; nt++) mma16(sacc[nt], qf[ks], bf[nt]);
        }

        // ---- register softmax, base-2 (rows r0, r0+8; quad owns a row) ----
        float mx0 = -1e30f, mx1 = -1e30f;
#pragma unroll
        for (int nt = 0; nt < 8; nt++) {
            mx0 = fmaxf(mx0, fmaxf(sacc[nt][0], sacc[nt][1]));
            mx1 = fmaxf(mx1, fmaxf(sacc[nt][2], sacc[nt][3]));
        }
        mx0 = fmaxf(mx0, __shfl_xor_sync(0xffffffffu, mx0, 1));
        mx0 = fmaxf(mx0, __shfl_xor_sync(0xffffffffu, mx0, 2));
        mx1 = fmaxf(mx1, __shfl_xor_sync(0xffffffffu, mx1, 1));
        mx1 = fmaxf(mx1, __shfl_xor_sync(0xffffffffu, mx1, 2));
        float mn0 = fmaxf(m0, mx0), mn1 = fmaxf(m1, mx1);
        float ss0 = 0.f, ss1 = 0.f;
#pragma unroll
        for (int nt = 0; nt < 8; nt++) {
            sacc[nt][0] = exp2f(sacc[nt][0] - mn0);
            sacc[nt][1] = exp2f(sacc[nt][1] - mn0);
            sacc[nt][2] = exp2f(sacc[nt][2] - mn1);
            sacc[nt][3] = exp2f(sacc[nt][3] - mn1);
            ss0 += sacc[nt][0] + sacc[nt][1];
            ss1 += sacc[nt][2] + sacc[nt][3];
        }
        ss0 += __shfl_xor_sync(0xffffffffu, ss0, 1);
        ss0 += __shfl_xor_sync(0xffffffffu, ss0, 2);
        ss1 += __shfl_xor_sync(0xffffffffu, ss1, 1);
        ss1 += __shfl_xor_sync(0xffffffffu, ss1, 2);
        float c0 = exp2f(m0 - mn0), c1 = exp2f(m1 - mn1);
        l0 = l0 * c0 + ss0; l1 = l1 * c1 + ss1;
        m0 = mn0; m1 = mn1;

        // ---- scale accO; pack P to fp16 A-fragments (identity re-layout) ----
#pragma unroll
        for (int nt = 0; nt < 16; nt++) {
            accO[nt][0] *= c0; accO[nt][1] *= c0;
            accO[nt][2] *= c1; accO[nt][3] *= c1;
        }
        uint32_t ph[4][4];
#pragma unroll
        for (int ks = 0; ks < 4; ks++) {
            ph[ks][0] = pack_h2(sacc[2 * ks][0], sacc[2 * ks][1]);
            ph[ks][1] = pack_h2(sacc[2 * ks][2], sacc[2 * ks][3]);
            ph[ks][2] = pack_h2(sacc[2 * ks + 1][0], sacc[2 * ks + 1][1]);
            ph[ks][3] = pack_h2(sacc[2 * ks + 1][2], sacc[2 * ks + 1][3]);
        }

        // ---- O += P @ V (warp: its 16 q-rows x all 128 d-cols) ----
#pragma unroll
        for (int ks = 0; ks < 4; ks++) {
            uint32_t bf[16][2];
#pragma unroll
            for (int p = 0; p < 8; p++) {
                uint32_t r0w, r1w, r2w, r3w;
                ldsm4t(r0w, r1w, r2w, r3w,
                       vbase + (uint32_t)((ks * 16 + lrow) * KPB + p * 32) + hi16);
                bf[2 * p][0] = r0w; bf[2 * p][1] = r1w;
                bf[2 * p + 1][0] = r2w; bf[2 * p + 1][1] = r3w;
            }
#pragma unroll
            for (int nt = 0; nt < 16; nt++) mma16(accO[nt], ph[ks], bf[nt]);
        }
    }

    // ---- write O (fp16, consumed by Wo GEMM); stats are in registers ----
    float i0 = 1.f / l0, i1 = 1.f / l1;
    __half* op  = g_attnh + (size_t)(b * Q_ + q0 + r0) * (H_ * D_) + h * D_;
    __half* op8 = op + (size_t)8 * (H_ * D_);
#pragma unroll
    for (int nt = 0; nt < 16; nt++) {
        *(__half2*)(op  + nt * 8 + 2 * t) =
            __floats2half2_rn(accO[nt][0] * i0, accO[nt][1] * i0);
        *(__half2*)(op8 + nt * 8 + 2 * t) =
            __floats2half2_rn(accO[nt][2] * i1, accO[nt][3] * i1);
    }
#undef KV_ISSUE
}

// ---------------------------------------------------------------------------
extern "C" void kernel_launch(void* const* d_in, const int* in_sizes, int n_in,
                              void* d_out, int out_size)
{
    const float* hidden = (const float*)d_in[0];
    const float* cosp   = (const float*)d_in[1];
    const float* sinp   = (const float*)d_in[2];
    const float* mask   = (const float*)d_in[3];
    const float* ck     = (const float*)d_in[4];
    const float* cv     = (const float*)d_in[5];
    const int*   sink   = (const int*)d_in[6];
    const float* Wq     = (const float*)d_in[7];
    const float* Wk     = (const float*)d_in[8];
    const float* Wv     = (const float*)d_in[9];
    const float* Wo     = (const float*)d_in[10];
    float* out = (float*)d_out;

    float  *qkv_p = nullptr;
    __half *hidh_p = nullptr, *wh_p = nullptr, *woh_p = nullptr;
    __half *attnh_p = nullptr, *mh_p = nullptr;
    cudaGetSymbolAddress((void**)&qkv_p, g_qkv);
    cudaGetSymbolAddress((void**)&hidh_p, g_hidh);
    cudaGetSymbolAddress((void**)&wh_p, g_wh);
    cudaGetSymbolAddress((void**)&woh_p, g_woh);
    cudaGetSymbolAddress((void**)&attnh_p, g_attnh);
    cudaGetSymbolAddress((void**)&mh_p, g_mh);

    // fp32 -> fp16 conversions (bandwidth-bound)
    {
        int n4h = M_ * HID_ / 4;
        cvt_half_k<<<(n4h + 255) / 256, 256>>>((const float4*)hidden, (__half2*)hidh_p, n4h);
        int n4q = H_ * D_ * HID_ / 4;
        cvt_half_k<<<(n4q + 255) / 256, 256>>>((const float4*)Wq, (__half2*)wh_p, n4q);
        int n4k = KVH_ * D_ * HID_ / 4;
        cvt_half_k<<<(n4k + 255) / 256, 256>>>((const float4*)Wk,
            (__half2*)(wh_p + (size_t)H_ * D_ * HID_), n4k);
        cvt_half_k<<<(n4k + 255) / 256, 256>>>((const float4*)Wv,
            (__half2*)(wh_p + (size_t)(H_ + KVH_) * D_ * HID_), n4k);
        int n4o = HID_ * H_ * D_ / 4;
        cvt_half_k<<<(n4o + 255) / 256, 256>>>((const float4*)Wo, (__half2*)woh_p, n4o);
        int n4m = B_ * Q_ * KV_ / 4;
        cvt_mask_k<<<(n4m + 255) / 256, 256>>>((const float4*)mask, (__half2*)mh_p, n4m);
    }

    const int smem_gemm = 4 * (SAB + SBB);   // 122880 B
    cudaFuncSetAttribute(gemm_h, cudaFuncAttributeMaxDynamicSharedMemorySize, smem_gemm);

    // Fused QKV projection
    gemm_h<<<dim3(QKVN_ / 128, M_ / 256), 256, smem_gemm>>>(
        hidh_p, wh_p, qkv_p, HID_, QKVN_);

    // KV cache copy (fp16) + RoPE/scatter (fp16)
    copy_caches<<<2048, 256>>>((const float4*)ck, (const float4*)cv);
    {
        int total = B_ * Q_ * (H_ + 2 * KVH_) * D_;
        rope_scatter<<<(total + 255) / 256, 256>>>(cosp, sinp, sink);
    }

    // Attention: 64-row CTAs, 2 CTAs/SM
    cudaFuncSetAttribute(attn_h, cudaFuncAttributeMaxDynamicSharedMemorySize, ATTN_SMEM);
    attn_h<<<dim3(Q_ / 64, H_, B_), 128, ATTN_SMEM>>>(mh_p);

    // Output projection -> d_out
    gemm_h<<<dim3(HID_ / 128, M_ / 256), 256, smem_gemm>>>(
        attnh_p, woh_p, out, H_ * D_, HID_);
}